// round 1
// baseline (speedup 1.0000x reference)
#include <cuda_runtime.h>
#include <cuda_bf16.h>
#include <cstdint>

#define NROWS 8192
#define IN_DIM 128
#define HID 64

// ---------------- scratch (static device globals; no allocation) ----------------
__device__ __align__(16) float g_struct[NROWS * HID];      // relu(x@fea_W+b)
__device__ __align__(16) float g_Wh[NROWS * IN_DIM];       // structure@gat_W
__device__ __align__(16) float g_s1[NROWS];
__device__ __align__(16) float g_s2[NROWS];
__device__ unsigned g_s2max_bits;
__device__ __align__(16) float g_gates[NROWS * 512];       // enc gates (256) then dec gates (512)
__device__ __align__(16) float g_henc[NROWS * HID];
__device__ __align__(16) float g_emb[NROWS * IN_DIM];

// ---------------- helpers ----------------
__device__ __forceinline__ float sigmoidf_(float x) { return 1.0f / (1.0f + __expf(-x)); }

__device__ __forceinline__ unsigned float_key(float f) {
    unsigned b = __float_as_uint(f);
    return (b & 0x80000000u) ? ~b : (b | 0x80000000u);
}
__device__ __forceinline__ float key_float(unsigned k) {
    unsigned b = (k & 0x80000000u) ? (k & 0x7fffffffu) : ~k;
    return __uint_as_float(b);
}

// ---------------- small GEMM: C[M,N] = epi(A[M,K] @ B + bias) ----------------
// 256 threads, 16 rows of A per block. BTRANS: B[k,n] = W[n*K+k] (i.e. A @ W.T)
template <int K, int N, int NCHUNK, bool BTRANS, int EPI>
__global__ void small_gemm(const float* __restrict__ A, const float* __restrict__ W,
                           const float* __restrict__ bias, float* __restrict__ C) {
    constexpr int RG = 256 / NCHUNK;   // row groups
    constexpr int R = 16 / RG;         // rows per thread
    __shared__ float As[16][K];
    const int i0 = blockIdx.x * 16;
    const int n0 = blockIdx.y * NCHUNK;
    const int n = n0 + (threadIdx.x % NCHUNK);
    const int rg = threadIdx.x / NCHUNK;

    for (int idx = threadIdx.x; idx < 16 * K; idx += 256) {
        As[idx / K][idx % K] = A[(size_t)(i0 + idx / K) * K + (idx % K)];
    }
    __syncthreads();

    float acc[R];
#pragma unroll
    for (int r = 0; r < R; r++) acc[r] = 0.f;

#pragma unroll 4
    for (int k = 0; k < K; k++) {
        float b = BTRANS ? W[(size_t)n * K + k] : W[(size_t)k * N + n];
#pragma unroll
        for (int r = 0; r < R; r++) acc[r] += As[rg * R + r][k] * b;
    }

    float bv = bias ? bias[n] : 0.f;
#pragma unroll
    for (int r = 0; r < R; r++) {
        float v = acc[r] + bv;
        if (EPI == 1) v = fmaxf(v, 0.f);  // relu
        C[(size_t)(i0 + rg * R + r) * N + n] = v;
    }
}

// ---------------- s2max init ----------------
__global__ void init_kernel() { g_s2max_bits = 0u; }

// ---------------- s1 = Wh@a1, s2 = Wh@a2, global max(s2) ----------------
__global__ void s1s2_kernel(const float* __restrict__ gat_a) {
    int warp = threadIdx.x >> 5, lane = threadIdx.x & 31;
    int row = blockIdx.x * 8 + warp;
    const float* w = g_Wh + (size_t)row * IN_DIM;
    float v1 = 0.f, v2 = 0.f;
#pragma unroll
    for (int k = lane; k < IN_DIM; k += 32) {
        float x = w[k];
        v1 += x * gat_a[k];
        v2 += x * gat_a[IN_DIM + k];
    }
#pragma unroll
    for (int off = 16; off; off >>= 1) {
        v1 += __shfl_xor_sync(0xffffffffu, v1, off);
        v2 += __shfl_xor_sync(0xffffffffu, v2, off);
    }
    __shared__ float smax[8];
    if (lane == 0) {
        g_s1[row] = v1;
        g_s2[row] = v2;
        smax[warp] = v2;
    }
    __syncthreads();
    if (threadIdx.x == 0) {
        float m = smax[0];
#pragma unroll
        for (int i = 1; i < 8; i++) m = fmaxf(m, smax[i]);
        atomicMax(&g_s2max_bits, float_key(m));
    }
}

// ---------------- LSTM elementwise (h0 = c0 = 0) ----------------
template <int H>
__global__ void lstm_kernel(const float* __restrict__ gates, const float* __restrict__ b_ih,
                            const float* __restrict__ b_hh, float* __restrict__ h) {
    int idx = blockIdx.x * blockDim.x + threadIdx.x;
    if (idx >= NROWS * H) return;
    int row = idx / H, hc = idx % H;
    const float* g = gates + (size_t)row * 4 * H;
    float gi = g[hc] + b_ih[hc] + b_hh[hc];
    float gg = g[2 * H + hc] + b_ih[2 * H + hc] + b_hh[2 * H + hc];
    float go = g[3 * H + hc] + b_ih[3 * H + hc] + b_hh[3 * H + hc];
    float c = sigmoidf_(gi) * tanhf(gg);
    h[idx] = sigmoidf_(go) * tanhf(c);
}

// ---------------- fused masked softmax-attention GEMM: emb = elu(softmax(scores) @ Wh) ----------------
// BM=32 rows per block, BK=32 j per chunk, 256 threads. acc 4x4 per thread over 32x128 tile.
__global__ __launch_bounds__(256) void attn_emb_kernel(const float* __restrict__ adj) {
    __shared__ float p_s[32 * 33];
    __shared__ float4 wh_s[32 * 32];
    __shared__ float s1_s[32], m_s[32], den_s[32];

    const int i0 = blockIdx.x * 32;
    const int tid = threadIdx.x;
    if (tid < 32) {
        float s2m = key_float(g_s2max_bits);
        float v = g_s1[i0 + tid];
        s1_s[tid] = v;
        float e = v + s2m;
        m_s[tid] = e > 0.f ? e : 0.2f * e;
    }
    __syncthreads();

    const int cg = tid & 31;   // column group (4 cols)
    const int rg = tid >> 5;   // 0..7
    float acc[4][4];
#pragma unroll
    for (int a = 0; a < 4; a++)
#pragma unroll
        for (int b = 0; b < 4; b++) acc[a][b] = 0.f;
    float den = 0.f;

    const float4* Wh4 = (const float4*)g_Wh;

    for (int jc = 0; jc < NROWS; jc += 32) {
        // p tile: 32x32
#pragma unroll
        for (int e = 0; e < 4; e++) {
            int idx = tid + e * 256;
            int r = idx >> 5, c = idx & 31;
            float aval = adj[(size_t)(i0 + r) * NROWS + jc + c];
            float ee = s1_s[r] + g_s2[jc + c];
            ee = ee > 0.f ? ee : 0.2f * ee;
            p_s[r * 33 + c] = (aval > 0.f) ? __expf(ee - m_s[r]) : 0.f;
        }
        // Wh tile: 32 rows x 128 cols (32 float4)
#pragma unroll
        for (int e = 0; e < 4; e++) {
            int idx = tid + e * 256;
            int r = idx >> 5, c4 = idx & 31;
            wh_s[r * 32 + c4] = Wh4[(size_t)(jc + r) * 32 + c4];
        }
        __syncthreads();

        if (tid < 32) {
#pragma unroll
            for (int c = 0; c < 32; c++) den += p_s[tid * 33 + c];
        }
#pragma unroll
        for (int k = 0; k < 32; k++) {
            float4 w = wh_s[k * 32 + cg];
#pragma unroll
            for (int rr = 0; rr < 4; rr++) {
                float p = p_s[(rr * 8 + rg) * 33 + k];
                acc[rr][0] += p * w.x;
                acc[rr][1] += p * w.y;
                acc[rr][2] += p * w.z;
                acc[rr][3] += p * w.w;
            }
        }
        __syncthreads();
    }

    if (tid < 32) den_s[tid] = den;
    __syncthreads();

#pragma unroll
    for (int rr = 0; rr < 4; rr++) {
        int r = rr * 8 + rg;
        float inv = 1.0f / den_s[r];
#pragma unroll
        for (int cc = 0; cc < 4; cc++) {
            float v = acc[rr][cc] * inv;
            v = v > 0.f ? v : expm1f(v);  // elu
            g_emb[(size_t)(i0 + r) * IN_DIM + cg * 4 + cc] = v;
        }
    }
}

// ---------------- con_adj = emb @ emb.T  (8192x8192, K=128) ----------------
// BM=BN=128, BK=16, 256 threads, 8x8 per thread.
__global__ __launch_bounds__(256) void syrk_kernel(float* __restrict__ out) {
    __shared__ float As[16][132];
    __shared__ float Bs[16][132];
    const int i0 = blockIdx.y * 128;
    const int j0 = blockIdx.x * 128;
    const int tid = threadIdx.x;
    const int tx = tid & 15, ty = tid >> 4;

    float acc[8][8];
#pragma unroll
    for (int i = 0; i < 8; i++)
#pragma unroll
        for (int j = 0; j < 8; j++) acc[i][j] = 0.f;

    const float4* E4 = (const float4*)g_emb;

    for (int kk = 0; kk < IN_DIM; kk += 16) {
#pragma unroll
        for (int e = 0; e < 2; e++) {
            int f = tid + e * 256;              // 0..511
            int row = f >> 2, c4 = f & 3;       // row 0..127, c4 0..3
            float4 va = E4[(size_t)(i0 + row) * 32 + (kk >> 2) + c4];
            As[c4 * 4 + 0][row] = va.x;
            As[c4 * 4 + 1][row] = va.y;
            As[c4 * 4 + 2][row] = va.z;
            As[c4 * 4 + 3][row] = va.w;
            float4 vb = E4[(size_t)(j0 + row) * 32 + (kk >> 2) + c4];
            Bs[c4 * 4 + 0][row] = vb.x;
            Bs[c4 * 4 + 1][row] = vb.y;
            Bs[c4 * 4 + 2][row] = vb.z;
            Bs[c4 * 4 + 3][row] = vb.w;
        }
        __syncthreads();

#pragma unroll
        for (int k = 0; k < 16; k++) {
            float4 a0 = *(const float4*)&As[k][ty * 8];
            float4 a1 = *(const float4*)&As[k][ty * 8 + 4];
            float4 b0 = *(const float4*)&Bs[k][tx * 8];
            float4 b1 = *(const float4*)&Bs[k][tx * 8 + 4];
            float a[8] = {a0.x, a0.y, a0.z, a0.w, a1.x, a1.y, a1.z, a1.w};
            float b[8] = {b0.x, b0.y, b0.z, b0.w, b1.x, b1.y, b1.z, b1.w};
#pragma unroll
            for (int i = 0; i < 8; i++)
#pragma unroll
                for (int j = 0; j < 8; j++) acc[i][j] += a[i] * b[j];
        }
        __syncthreads();
    }

#pragma unroll
    for (int i = 0; i < 8; i++) {
        size_t row = (size_t)(i0 + ty * 8 + i);
        float4* orow = (float4*)(out + row * NROWS);
        orow[(j0 >> 2) + tx * 2] = make_float4(acc[i][0], acc[i][1], acc[i][2], acc[i][3]);
        orow[(j0 >> 2) + tx * 2 + 1] = make_float4(acc[i][4], acc[i][5], acc[i][6], acc[i][7]);
    }
}

// ---------------- launch ----------------
extern "C" void kernel_launch(void* const* d_in, const int* in_sizes, int n_in,
                              void* d_out, int out_size) {
    const float* x = (const float*)d_in[0];
    const float* adj = (const float*)d_in[1];
    const float* fea_W = (const float*)d_in[2];
    const float* fea_b = (const float*)d_in[3];
    const float* gat_W = (const float*)d_in[4];
    const float* gat_a = (const float*)d_in[5];
    const float* enc_W_ih = (const float*)d_in[6];
    // d_in[7] enc_W_hh unused (h0 = 0)
    const float* enc_b_ih = (const float*)d_in[8];
    const float* enc_b_hh = (const float*)d_in[9];
    const float* dec_W_ih = (const float*)d_in[10];
    // d_in[11] dec_W_hh unused (h0 = 0)
    const float* dec_b_ih = (const float*)d_in[12];
    const float* dec_b_hh = (const float*)d_in[13];

    float* out = (float*)d_out;
    float* con_adj = out;                                      // [8192, 8192]
    float* att_adj = out + (size_t)NROWS * NROWS;              // [8192, 128]

    float* p_struct;  cudaGetSymbolAddress((void**)&p_struct, g_struct);
    float* p_Wh;      cudaGetSymbolAddress((void**)&p_Wh, g_Wh);
    float* p_gates;   cudaGetSymbolAddress((void**)&p_gates, g_gates);
    float* p_henc;    cudaGetSymbolAddress((void**)&p_henc, g_henc);

    // 1. structure = relu(x @ fea_W + fea_b)          [8192,128]@[128,64]
    small_gemm<128, 64, 64, false, 1><<<dim3(NROWS / 16, 1), 256>>>(x, fea_W, fea_b, p_struct);
    // 2. Wh = structure @ gat_W                        [8192,64]@[64,128]
    small_gemm<64, 128, 128, false, 0><<<dim3(NROWS / 16, 1), 256>>>(p_struct, gat_W, nullptr, p_Wh);
    // 3. s1, s2, max(s2)
    init_kernel<<<1, 1>>>();
    s1s2_kernel<<<NROWS / 8, 256>>>(gat_a);
    // 4. encoder gates = x @ enc_W_ih.T                [8192,128]@[128,256]
    small_gemm<128, 256, 256, true, 0><<<dim3(NROWS / 16, 1), 256>>>(x, enc_W_ih, nullptr, p_gates);
    // 5. h_enc
    lstm_kernel<64><<<(NROWS * 64 + 255) / 256, 256>>>(p_gates, enc_b_ih, enc_b_hh, p_henc);
    // 6. decoder gates = h_enc @ dec_W_ih.T            [8192,64]@[64,512]
    small_gemm<64, 512, 256, true, 0><<<dim3(NROWS / 16, 2), 256>>>(p_henc, dec_W_ih, nullptr, p_gates);
    // 7. att_adj (direct to output)
    lstm_kernel<128><<<(NROWS * 128 + 255) / 256, 256>>>(p_gates, dec_b_ih, dec_b_hh, att_adj);
    // 8. emb = elu(softmax(masked lrelu(s1+s2)) @ Wh)
    attn_emb_kernel<<<NROWS / 32, 256>>>(adj);
    // 9. con_adj = emb @ emb.T
    syrk_kernel<<<dim3(NROWS / 128, NROWS / 128), 256>>>(con_adj);
}

// round 3
// speedup vs baseline: 1.0341x; 1.0341x over previous
#include <cuda_runtime.h>
#include <cuda_bf16.h>
#include <cstdint>

#define NROWS 8192
#define IN_DIM 128
#define HID 64

// ---------------- scratch (static device globals; no allocation) ----------------
__device__ __align__(16) float g_struct[NROWS * HID];
__device__ __align__(16) float g_Wh[NROWS * IN_DIM];
__device__ __align__(16) float g_s1[NROWS];
__device__ __align__(16) float g_s2[NROWS];
__device__ __align__(16) float g_A[NROWS];   // exp(s1+s2max - m) per row
__device__ __align__(16) float g_B[NROWS];   // exp(s2 - s2max) per col
__device__ __align__(16) float g_C[NROWS];   // exp(0.2*(s1+s2max) - m) per row
__device__ __align__(16) float g_D[NROWS];   // exp(0.2*(s2 - s2max)) per col
__device__ unsigned g_s2max_bits;
__device__ __align__(16) float g_gates[NROWS * 512];
__device__ __align__(16) float g_henc[NROWS * HID];
__device__ __align__(16) float g_emb[NROWS * IN_DIM];

// ---------------- helpers ----------------
__device__ __forceinline__ float sigmoidf_(float x) { return 1.0f / (1.0f + __expf(-x)); }

__device__ __forceinline__ unsigned float_key(float f) {
    unsigned b = __float_as_uint(f);
    return (b & 0x80000000u) ? ~b : (b | 0x80000000u);
}
__device__ __forceinline__ float key_float(unsigned k) {
    unsigned b = (k & 0x80000000u) ? (k & 0x7fffffffu) : ~k;
    return __uint_as_float(b);
}

// packed f32x2 (Blackwell): 2 FMAs per instruction on the fma pipe
__device__ __forceinline__ unsigned long long pack2(float lo, float hi) {
    unsigned long long r;
    asm("mov.b64 %0, {%1, %2};" : "=l"(r) : "f"(lo), "f"(hi));
    return r;
}
__device__ __forceinline__ void ffma2(unsigned long long& d, unsigned long long a, unsigned long long b) {
    asm("fma.rn.f32x2 %0, %1, %2, %3;" : "=l"(d) : "l"(a), "l"(b), "l"(d));
}
__device__ __forceinline__ float2 unpack2(unsigned long long v) {
    float2 r;
    asm("mov.b64 {%0, %1}, %2;" : "=f"(r.x), "=f"(r.y) : "l"(v));
    return r;
}

// ---------------- small GEMM: C[M,N] = epi(A[M,K] @ B + bias) ----------------
template <int K, int N, int NCHUNK, bool BTRANS, int EPI>
__global__ void small_gemm(const float* __restrict__ A, const float* __restrict__ W,
                           const float* __restrict__ bias, float* __restrict__ C) {
    constexpr int RG = 256 / NCHUNK;
    constexpr int R = 16 / RG;
    __shared__ float As[16][K];
    const int i0 = blockIdx.x * 16;
    const int n0 = blockIdx.y * NCHUNK;
    const int n = n0 + (threadIdx.x % NCHUNK);
    const int rg = threadIdx.x / NCHUNK;

    for (int idx = threadIdx.x; idx < 16 * K; idx += 256) {
        As[idx / K][idx % K] = A[(size_t)(i0 + idx / K) * K + (idx % K)];
    }
    __syncthreads();

    float acc[R];
#pragma unroll
    for (int r = 0; r < R; r++) acc[r] = 0.f;

#pragma unroll 4
    for (int k = 0; k < K; k++) {
        float b = BTRANS ? W[(size_t)n * K + k] : W[(size_t)k * N + n];
#pragma unroll
        for (int r = 0; r < R; r++) acc[r] += As[rg * R + r][k] * b;
    }

    float bv = bias ? bias[n] : 0.f;
#pragma unroll
    for (int r = 0; r < R; r++) {
        float v = acc[r] + bv;
        if (EPI == 1) v = fmaxf(v, 0.f);
        C[(size_t)(i0 + rg * R + r) * N + n] = v;
    }
}

__global__ void init_kernel() { g_s2max_bits = 0u; }

// ---------------- s1 = Wh@a1, s2 = Wh@a2, global max(s2) ----------------
__global__ void s1s2_kernel(const float* __restrict__ gat_a) {
    int warp = threadIdx.x >> 5, lane = threadIdx.x & 31;
    int row = blockIdx.x * 8 + warp;
    const float* w = g_Wh + (size_t)row * IN_DIM;
    float v1 = 0.f, v2 = 0.f;
#pragma unroll
    for (int k = lane; k < IN_DIM; k += 32) {
        float x = w[k];
        v1 += x * gat_a[k];
        v2 += x * gat_a[IN_DIM + k];
    }
#pragma unroll
    for (int off = 16; off; off >>= 1) {
        v1 += __shfl_xor_sync(0xffffffffu, v1, off);
        v2 += __shfl_xor_sync(0xffffffffu, v2, off);
    }
    __shared__ float smax[8];
    if (lane == 0) {
        g_s1[row] = v1;
        g_s2[row] = v2;
        smax[warp] = v2;
    }
    __syncthreads();
    if (threadIdx.x == 0) {
        float m = smax[0];
#pragma unroll
        for (int i = 1; i < 8; i++) m = fmaxf(m, smax[i]);
        atomicMax(&g_s2max_bits, float_key(m));
    }
}

// ---------------- precompute A,B,C,D factor vectors ----------------
__global__ void vec_kernel() {
    int i = blockIdx.x * 256 + threadIdx.x;
    float s2max = key_float(g_s2max_bits);
    float t = g_s1[i] + s2max;
    float m = t > 0.f ? t : 0.2f * t;         // m_i = lrelu(s1_i + s2max) >= row max
    g_A[i] = expf(t - m);
    g_C[i] = expf(0.2f * t - m);
    float u = g_s2[i] - s2max;                // <= 0
    g_B[i] = expf(u);
    g_D[i] = expf(0.2f * u);
}

// ---------------- LSTM elementwise (h0 = c0 = 0) ----------------
template <int H>
__global__ void lstm_kernel(const float* __restrict__ gates, const float* __restrict__ b_ih,
                            const float* __restrict__ b_hh, float* __restrict__ h) {
    int idx = blockIdx.x * blockDim.x + threadIdx.x;
    if (idx >= NROWS * H) return;
    int row = idx / H, hc = idx % H;
    const float* g = gates + (size_t)row * 4 * H;
    float gi = g[hc] + b_ih[hc] + b_hh[hc];
    float gg = g[2 * H + hc] + b_ih[2 * H + hc] + b_hh[2 * H + hc];
    float go = g[3 * H + hc] + b_ih[3 * H + hc] + b_hh[3 * H + hc];
    float c = sigmoidf_(gi) * tanhf(gg);
    h[idx] = sigmoidf_(go) * tanhf(c);
}

// ---------------- fused masked softmax-attention GEMM ----------------
// emb = elu(softmax(mask(lrelu(s1+s2))) @ Wh).  No exp in hot loop: p = A_i*B_j or C_i*D_j.
// BM=32 rows/block, 128 threads, thread tile 4 rows x 8 cols, FFMA2 inner loop.
__global__ __launch_bounds__(128) void attn_emb_kernel(const float* __restrict__ adj) {
    __shared__ float p_s[32 * 36];                 // [r][k], stride 36
    __shared__ __align__(16) float wh_s[32 * 128]; // [k][c]
    __shared__ float s1_s[32], A_s[32], C_s[32], den_s[32];

    const int i0 = blockIdx.x * 32;
    const int tid = threadIdx.x;
    if (tid < 32) {
        s1_s[tid] = g_s1[i0 + tid];
        A_s[tid] = g_A[i0 + tid];
        C_s[tid] = g_C[i0 + tid];
    }

    const int cg = tid & 15;        // GEMM: cols cg*8 .. cg*8+7
    const int rg = tid >> 4;        // GEMM: rows rg*4 .. rg*4+3
    const int c4 = (tid & 7) * 4;   // build: col quad
    const int rp = tid >> 3;        // build: rows rp*2, rp*2+1

    unsigned long long acc[4][4];
#pragma unroll
    for (int a = 0; a < 4; a++)
#pragma unroll
        for (int b = 0; b < 4; b++) acc[a][b] = 0ull;
    float den = 0.f;

    const float4* Wh4 = (const float4*)g_Wh;
    const float4* S24 = (const float4*)g_s2;
    const float4* B4 = (const float4*)g_B;
    const float4* D4 = (const float4*)g_D;

    for (int jc = 0; jc < NROWS; jc += 32) {
        __syncthreads();   // previous GEMM done reading p_s / wh_s

        // load Wh tile: 32 k-rows x 128 cols = 1024 float4, one per (tid,e) slot
#pragma unroll
        for (int e = 0; e < 8; e++) {
            int idx = tid + e * 128;            // 0..1023
            int k = idx >> 5, q = idx & 31;     // k row 0..31, float4 col 0..31
            ((float4*)wh_s)[k * 32 + q] = Wh4[(size_t)(jc + k) * 32 + q];
        }

        // build p tile (32x32): factorized exp, no MUFU
        {
            float4 s2v = S24[(jc >> 2) + (tid & 7)];
            float4 Bv = B4[(jc >> 2) + (tid & 7)];
            float4 Dv = D4[(jc >> 2) + (tid & 7)];
#pragma unroll
            for (int rr = 0; rr < 2; rr++) {
                int r = rp * 2 + rr;
                float4 av = *(const float4*)&adj[(size_t)(i0 + r) * NROWS + jc + c4];
                float s1 = s1_s[r], Av = A_s[r], Cv = C_s[r];
                float4 pv;
                {
                    float t = s1 + s2v.x;
                    pv.x = (av.x > 0.f) ? (t > 0.f ? Av * Bv.x : Cv * Dv.x) : 0.f;
                }
                {
                    float t = s1 + s2v.y;
                    pv.y = (av.y > 0.f) ? (t > 0.f ? Av * Bv.y : Cv * Dv.y) : 0.f;
                }
                {
                    float t = s1 + s2v.z;
                    pv.z = (av.z > 0.f) ? (t > 0.f ? Av * Bv.z : Cv * Dv.z) : 0.f;
                }
                {
                    float t = s1 + s2v.w;
                    pv.w = (av.w > 0.f) ? (t > 0.f ? Av * Bv.w : Cv * Dv.w) : 0.f;
                }
                *(float4*)&p_s[r * 36 + c4] = pv;
            }
        }
        __syncthreads();

        // denominator: one thread per row
        if (tid < 32) {
            float d = 0.f;
#pragma unroll
            for (int c = 0; c < 32; c++) d += p_s[tid * 36 + c];
            den += d;
        }

        // GEMM: acc += p(32x32) @ wh(32x128), FFMA2
#pragma unroll 8
        for (int k = 0; k < 32; k++) {
            const unsigned long long* w64 = (const unsigned long long*)&wh_s[k * 128 + cg * 8];
            unsigned long long b0 = w64[0], b1 = w64[1], b2 = w64[2], b3 = w64[3];
#pragma unroll
            for (int rr = 0; rr < 4; rr++) {
                float p = p_s[(rg * 4 + rr) * 36 + k];
                unsigned long long pp = pack2(p, p);
                ffma2(acc[rr][0], pp, b0);
                ffma2(acc[rr][1], pp, b1);
                ffma2(acc[rr][2], pp, b2);
                ffma2(acc[rr][3], pp, b3);
            }
        }
    }

    if (tid < 32) den_s[tid] = den;
    __syncthreads();

#pragma unroll
    for (int rr = 0; rr < 4; rr++) {
        int r = rg * 4 + rr;
        float inv = 1.0f / den_s[r];
        float o[8];
#pragma unroll
        for (int j4 = 0; j4 < 4; j4++) {
            float2 v = unpack2(acc[rr][j4]);
            o[j4 * 2] = v.x * inv;
            o[j4 * 2 + 1] = v.y * inv;
        }
#pragma unroll
        for (int j = 0; j < 8; j++) o[j] = o[j] > 0.f ? o[j] : expm1f(o[j]);
        float4* orow = (float4*)&g_emb[(size_t)(i0 + r) * IN_DIM + cg * 8];
        orow[0] = make_float4(o[0], o[1], o[2], o[3]);
        orow[1] = make_float4(o[4], o[5], o[6], o[7]);
    }
}

// ---------------- con_adj = emb @ emb.T  (symmetric: only bi<=bj, mirror write) ----------------
__global__ __launch_bounds__(256) void syrk_kernel(float* __restrict__ out) {
    const int bi = blockIdx.y, bj = blockIdx.x;
    if (bj < bi) return;

    __shared__ __align__(16) float As[16][132];
    __shared__ __align__(16) float Bs[16][132];
    const int i0 = bi * 128;
    const int j0 = bj * 128;
    const int tid = threadIdx.x;
    const int tx = tid & 15, ty = tid >> 4;

    unsigned long long acc2[8][4];
#pragma unroll
    for (int i = 0; i < 8; i++)
#pragma unroll
        for (int j = 0; j < 4; j++) acc2[i][j] = 0ull;

    const float4* E4 = (const float4*)g_emb;

    for (int kk = 0; kk < IN_DIM; kk += 16) {
#pragma unroll
        for (int e = 0; e < 2; e++) {
            int f = tid + e * 256;
            int row = f >> 2, cq = f & 3;
            float4 va = E4[(size_t)(i0 + row) * 32 + (kk >> 2) + cq];
            As[cq * 4 + 0][row] = va.x;
            As[cq * 4 + 1][row] = va.y;
            As[cq * 4 + 2][row] = va.z;
            As[cq * 4 + 3][row] = va.w;
            float4 vb = E4[(size_t)(j0 + row) * 32 + (kk >> 2) + cq];
            Bs[cq * 4 + 0][row] = vb.x;
            Bs[cq * 4 + 1][row] = vb.y;
            Bs[cq * 4 + 2][row] = vb.z;
            Bs[cq * 4 + 3][row] = vb.w;
        }
        __syncthreads();

#pragma unroll 8
        for (int k = 0; k < 16; k++) {
            float4 a0 = *(const float4*)&As[k][ty * 8];
            float4 a1 = *(const float4*)&As[k][ty * 8 + 4];
            const unsigned long long* b64 = (const unsigned long long*)&Bs[k][tx * 8];
            unsigned long long b0 = b64[0], b1 = b64[1], b2 = b64[2], b3 = b64[3];
            float av[8] = {a0.x, a0.y, a0.z, a0.w, a1.x, a1.y, a1.z, a1.w};
#pragma unroll
            for (int i = 0; i < 8; i++) {
                unsigned long long ap = pack2(av[i], av[i]);
                ffma2(acc2[i][0], ap, b0);
                ffma2(acc2[i][1], ap, b1);
                ffma2(acc2[i][2], ap, b2);
                ffma2(acc2[i][3], ap, b3);
            }
        }
        __syncthreads();
    }

    float acc[8][8];
#pragma unroll
    for (int i = 0; i < 8; i++)
#pragma unroll
        for (int j4 = 0; j4 < 4; j4++) {
            float2 v = unpack2(acc2[i][j4]);
            acc[i][j4 * 2] = v.x;
            acc[i][j4 * 2 + 1] = v.y;
        }

    // normal tile
#pragma unroll
    for (int i = 0; i < 8; i++) {
        size_t row = (size_t)(i0 + ty * 8 + i);
        float4* orow = (float4*)(out + row * NROWS);
        orow[(j0 >> 2) + tx * 2] = make_float4(acc[i][0], acc[i][1], acc[i][2], acc[i][3]);
        orow[(j0 >> 2) + tx * 2 + 1] = make_float4(acc[i][4], acc[i][5], acc[i][6], acc[i][7]);
    }
    // mirror tile (transpose)
    if (bi != bj) {
#pragma unroll
        for (int j = 0; j < 8; j++) {
            size_t row = (size_t)(j0 + tx * 8 + j);
            float4* orow = (float4*)(out + row * NROWS);
            orow[(i0 >> 2) + ty * 2] = make_float4(acc[0][j], acc[1][j], acc[2][j], acc[3][j]);
            orow[(i0 >> 2) + ty * 2 + 1] = make_float4(acc[4][j], acc[5][j], acc[6][j], acc[7][j]);
        }
    }
}

// ---------------- launch ----------------
extern "C" void kernel_launch(void* const* d_in, const int* in_sizes, int n_in,
                              void* d_out, int out_size) {
    const float* x = (const float*)d_in[0];
    const float* adj = (const float*)d_in[1];
    const float* fea_W = (const float*)d_in[2];
    const float* fea_b = (const float*)d_in[3];
    const float* gat_W = (const float*)d_in[4];
    const float* gat_a = (const float*)d_in[5];
    const float* enc_W_ih = (const float*)d_in[6];
    const float* enc_b_ih = (const float*)d_in[8];
    const float* enc_b_hh = (const float*)d_in[9];
    const float* dec_W_ih = (const float*)d_in[10];
    const float* dec_b_ih = (const float*)d_in[12];
    const float* dec_b_hh = (const float*)d_in[13];

    float* out = (float*)d_out;
    float* con_adj = out;
    float* att_adj = out + (size_t)NROWS * NROWS;

    float* p_struct;  cudaGetSymbolAddress((void**)&p_struct, g_struct);
    float* p_Wh;      cudaGetSymbolAddress((void**)&p_Wh, g_Wh);
    float* p_gates;   cudaGetSymbolAddress((void**)&p_gates, g_gates);
    float* p_henc;    cudaGetSymbolAddress((void**)&p_henc, g_henc);

    small_gemm<128, 64, 64, false, 1><<<dim3(NROWS / 16, 1), 256>>>(x, fea_W, fea_b, p_struct);
    small_gemm<64, 128, 128, false, 0><<<dim3(NROWS / 16, 1), 256>>>(p_struct, gat_W, nullptr, p_Wh);
    init_kernel<<<1, 1>>>();
    s1s2_kernel<<<NROWS / 8, 256>>>(gat_a);
    vec_kernel<<<NROWS / 256, 256>>>();
    small_gemm<128, 256, 256, true, 0><<<dim3(NROWS / 16, 1), 256>>>(x, enc_W_ih, nullptr, p_gates);
    lstm_kernel<64><<<(NROWS * 64 + 255) / 256, 256>>>(p_gates, enc_b_ih, enc_b_hh, p_henc);
    small_gemm<64, 512, 256, true, 0><<<dim3(NROWS / 16, 2), 256>>>(p_henc, dec_W_ih, nullptr, p_gates);
    lstm_kernel<128><<<(NROWS * 128 + 255) / 256, 256>>>(p_gates, dec_b_ih, dec_b_hh, att_adj);
    attn_emb_kernel<<<NROWS / 32, 128>>>(adj);
    syrk_kernel<<<dim3(64, 64), 256>>>(con_adj);
}

// round 4
// speedup vs baseline: 1.4150x; 1.3684x over previous
#include <cuda_runtime.h>
#include <cuda_bf16.h>
#include <cstdint>

#define NROWS 8192
#define IN_DIM 128
#define HID 64

// ---------------- scratch (static device globals; no allocation) ----------------
__device__ __align__(16) float g_struct[NROWS * HID];
__device__ __align__(16) float g_Wh[NROWS * IN_DIM];
__device__ __align__(16) float g_s1[NROWS];
__device__ __align__(16) float g_s2[NROWS];
__device__ __align__(16) float g_A[NROWS];
__device__ __align__(16) float g_B[NROWS];
__device__ __align__(16) float g_C[NROWS];
__device__ __align__(16) float g_D[NROWS];
__device__ unsigned g_s2max_bits = 0u;   // atomicMax is idempotent -> replay-deterministic
__device__ __align__(16) float g_henc[NROWS * HID];
__device__ __align__(16) float g_emb[NROWS * IN_DIM];

// ---------------- helpers ----------------
__device__ __forceinline__ float sigmoidf_(float x) { return 1.0f / (1.0f + __expf(-x)); }

__device__ __forceinline__ unsigned float_key(float f) {
    unsigned b = __float_as_uint(f);
    return (b & 0x80000000u) ? ~b : (b | 0x80000000u);
}
__device__ __forceinline__ float key_float(unsigned k) {
    unsigned b = (k & 0x80000000u) ? (k & 0x7fffffffu) : ~k;
    return __uint_as_float(b);
}

typedef unsigned long long ull;
__device__ __forceinline__ ull pack2(float lo, float hi) {
    ull r;
    asm("mov.b64 %0, {%1, %2};" : "=l"(r) : "f"(lo), "f"(hi));
    return r;
}
__device__ __forceinline__ void ffma2(ull& d, ull a, ull b) {
    asm("fma.rn.f32x2 %0, %1, %2, %3;" : "=l"(d) : "l"(a), "l"(b), "l"(d));
}
__device__ __forceinline__ float2 unpack2(ull v) {
    float2 r;
    asm("mov.b64 {%0, %1}, %2;" : "=f"(r.x), "=f"(r.y) : "l"(v));
    return r;
}

// ---------------- 1. structure = relu(x @ fea_W + fea_b) ----------------
__global__ __launch_bounds__(256) void struct_kernel(const float* __restrict__ A,
                                                     const float* __restrict__ W,
                                                     const float* __restrict__ bias) {
    __shared__ float As[16][128];
    const int i0 = blockIdx.x * 16;
    const int tid = threadIdx.x;
    const int n = tid & 63, rg = tid >> 6;   // 4 row groups x 4 rows

    for (int idx = tid; idx < 16 * 128; idx += 256)
        As[idx >> 7][idx & 127] = A[(size_t)(i0 + (idx >> 7)) * 128 + (idx & 127)];
    __syncthreads();

    float acc[4] = {0.f, 0.f, 0.f, 0.f};
#pragma unroll 4
    for (int k = 0; k < 128; k++) {
        float b = W[(size_t)k * 64 + n];
#pragma unroll
        for (int r = 0; r < 4; r++) acc[r] += As[rg * 4 + r][k] * b;
    }
    float bv = bias[n];
#pragma unroll
    for (int r = 0; r < 4; r++)
        g_struct[(size_t)(i0 + rg * 4 + r) * 64 + n] = fmaxf(acc[r] + bv, 0.f);
}

// ---------------- 2. Wh = structure @ gat_W, fused s1/s2/max(s2) ----------------
__global__ __launch_bounds__(256) void wh_s1s2_kernel(const float* __restrict__ W,
                                                      const float* __restrict__ gat_a) {
    __shared__ float As[16][64];
    __shared__ float r1[8][8], r2[8][8];
    const int i0 = blockIdx.x * 16;
    const int tid = threadIdx.x;
    const int n = tid & 127, rg = tid >> 7;   // 2 row groups x 8 rows

    for (int idx = tid; idx < 16 * 64; idx += 256)
        As[idx >> 6][idx & 63] = g_struct[(size_t)(i0 + (idx >> 6)) * 64 + (idx & 63)];
    __syncthreads();

    float acc[8];
#pragma unroll
    for (int r = 0; r < 8; r++) acc[r] = 0.f;
#pragma unroll 4
    for (int k = 0; k < 64; k++) {
        float b = W[(size_t)k * 128 + n];
#pragma unroll
        for (int r = 0; r < 8; r++) acc[r] += As[rg * 8 + r][k] * b;
    }
#pragma unroll
    for (int r = 0; r < 8; r++)
        g_Wh[(size_t)(i0 + rg * 8 + r) * 128 + n] = acc[r];

    // s1 = Wh@a1, s2 = Wh@a2 for the 16 rows of this block (exact tree reduction)
    float a1v = gat_a[n], a2v = gat_a[128 + n];
    int warp = tid >> 5, lane = tid & 31;
#pragma unroll
    for (int r = 0; r < 8; r++) {
        float v1 = acc[r] * a1v, v2 = acc[r] * a2v;
#pragma unroll
        for (int off = 16; off; off >>= 1) {
            v1 += __shfl_xor_sync(0xffffffffu, v1, off);
            v2 += __shfl_xor_sync(0xffffffffu, v2, off);
        }
        if (lane == 0) { r1[warp][r] = v1; r2[warp][r] = v2; }
    }
    __syncthreads();
    if (tid < 16) {
        int rgg = tid >> 3, rr = tid & 7;
        float s1 = r1[rgg * 4 + 0][rr] + r1[rgg * 4 + 1][rr] + r1[rgg * 4 + 2][rr] + r1[rgg * 4 + 3][rr];
        float s2 = r2[rgg * 4 + 0][rr] + r2[rgg * 4 + 1][rr] + r2[rgg * 4 + 2][rr] + r2[rgg * 4 + 3][rr];
        g_s1[i0 + tid] = s1;
        g_s2[i0 + tid] = s2;
        float m = s2;
#pragma unroll
        for (int off = 8; off; off >>= 1) m = fmaxf(m, __shfl_xor_sync(0x0000ffffu, m, off));
        if (tid == 0) atomicMax(&g_s2max_bits, float_key(m));
    }
}

// ---------------- 3. precompute A,B,C,D ----------------
__global__ void vec_kernel() {
    int i = blockIdx.x * 256 + threadIdx.x;
    float s2max = key_float(g_s2max_bits);
    float t = g_s1[i] + s2max;
    float m = t > 0.f ? t : 0.2f * t;
    g_A[i] = expf(t - m);
    g_C[i] = expf(0.2f * t - m);
    float u = g_s2[i] - s2max;
    g_B[i] = expf(u);
    g_D[i] = expf(0.2f * u);
}

// ---------------- 4. fused masked-softmax attention GEMM ----------------
// emb = elu(softmax(mask(lrelu(s1+s2))) @ Wh); p = A_i*B_j / C_i*D_j (no MUFU in loop).
// 128 threads, tile 32x128; thread: 4 rows x (4+4 cols). Conflict-free b-loads.
__global__ __launch_bounds__(128) void attn_emb_kernel(const float* __restrict__ adj) {
    __shared__ float p_s[32 * 36];
    __shared__ __align__(16) float wh_s[32 * 128];
    __shared__ float s1_s[32], A_s[32], C_s[32], den_s[32];

    const int i0 = blockIdx.x * 32;
    const int tid = threadIdx.x;
    if (tid < 32) {
        s1_s[tid] = g_s1[i0 + tid];
        A_s[tid] = g_A[i0 + tid];
        C_s[tid] = g_C[i0 + tid];
    }

    const int cg = tid & 15;        // col chunks: cg*4 and 64+cg*4 (warp-contiguous)
    const int rg = tid >> 4;        // 8 row groups x 4 rows
    const int c4 = (tid & 7) * 4;   // p-build columns
    const int rp = tid >> 3;        // p-build rows rp*2, rp*2+1

    ull acc[4][4];
#pragma unroll
    for (int a = 0; a < 4; a++)
#pragma unroll
        for (int b = 0; b < 4; b++) acc[a][b] = 0ull;
    float dsum0 = 0.f, dsum1 = 0.f;

    const float4* Wh4 = (const float4*)g_Wh;
    const float4* S24 = (const float4*)g_s2;
    const float4* B4 = (const float4*)g_B;
    const float4* D4 = (const float4*)g_D;

    for (int jc = 0; jc < NROWS; jc += 32) {
        __syncthreads();

        // Wh tile: 32 k-rows x 128 cols
#pragma unroll
        for (int e = 0; e < 8; e++) {
            int idx = tid + e * 128;
            int k = idx >> 5, q = idx & 31;
            ((float4*)wh_s)[k * 32 + q] = Wh4[(size_t)(jc + k) * 32 + q];
        }

        // p tile (32x32) + denominator accumulation
        {
            float4 s2v = S24[(jc >> 2) + (tid & 7)];
            float4 Bv = B4[(jc >> 2) + (tid & 7)];
            float4 Dv = D4[(jc >> 2) + (tid & 7)];
#pragma unroll
            for (int rr = 0; rr < 2; rr++) {
                int r = rp * 2 + rr;
                float4 av = *(const float4*)&adj[(size_t)(i0 + r) * NROWS + jc + c4];
                float s1 = s1_s[r], Av = A_s[r], Cv = C_s[r];
                float4 pv;
                { float t = s1 + s2v.x; pv.x = (av.x > 0.f) ? (t > 0.f ? Av * Bv.x : Cv * Dv.x) : 0.f; }
                { float t = s1 + s2v.y; pv.y = (av.y > 0.f) ? (t > 0.f ? Av * Bv.y : Cv * Dv.y) : 0.f; }
                { float t = s1 + s2v.z; pv.z = (av.z > 0.f) ? (t > 0.f ? Av * Bv.z : Cv * Dv.z) : 0.f; }
                { float t = s1 + s2v.w; pv.w = (av.w > 0.f) ? (t > 0.f ? Av * Bv.w : Cv * Dv.w) : 0.f; }
                *(float4*)&p_s[r * 36 + c4] = pv;
                float s = (pv.x + pv.y) + (pv.z + pv.w);
                if (rr == 0) dsum0 += s; else dsum1 += s;
            }
        }
        __syncthreads();

        // acc += p(32x32) @ wh(32x128), FFMA2, conflict-free LDS
#pragma unroll 8
        for (int k = 0; k < 32; k++) {
            ulonglong2 b0 = *(const ulonglong2*)&wh_s[k * 128 + cg * 4];
            ulonglong2 b1 = *(const ulonglong2*)&wh_s[k * 128 + 64 + cg * 4];
#pragma unroll
            for (int rr = 0; rr < 4; rr++) {
                float p = p_s[(rg * 4 + rr) * 36 + k];
                ull pp = pack2(p, p);
                ffma2(acc[rr][0], pp, b0.x);
                ffma2(acc[rr][1], pp, b0.y);
                ffma2(acc[rr][2], pp, b1.x);
                ffma2(acc[rr][3], pp, b1.y);
            }
        }
    }

    // reduce denominators: 8 threads per row-pair (lanes rp*8..rp*8+7 contiguous)
#pragma unroll
    for (int off = 4; off; off >>= 1) {
        dsum0 += __shfl_down_sync(0xffffffffu, dsum0, off, 8);
        dsum1 += __shfl_down_sync(0xffffffffu, dsum1, off, 8);
    }
    if ((tid & 7) == 0) {
        den_s[rp * 2] = dsum0;
        den_s[rp * 2 + 1] = dsum1;
    }
    __syncthreads();

#pragma unroll
    for (int rr = 0; rr < 4; rr++) {
        int r = rg * 4 + rr;
        float inv = 1.0f / den_s[r];
        float2 v0 = unpack2(acc[rr][0]), v1 = unpack2(acc[rr][1]);
        float2 v2 = unpack2(acc[rr][2]), v3 = unpack2(acc[rr][3]);
        float o[8] = {v0.x * inv, v0.y * inv, v1.x * inv, v1.y * inv,
                      v2.x * inv, v2.y * inv, v3.x * inv, v3.y * inv};
#pragma unroll
        for (int j = 0; j < 8; j++) o[j] = o[j] > 0.f ? o[j] : expm1f(o[j]);
        *(float4*)&g_emb[(size_t)(i0 + r) * IN_DIM + cg * 4] = make_float4(o[0], o[1], o[2], o[3]);
        *(float4*)&g_emb[(size_t)(i0 + r) * IN_DIM + 64 + cg * 4] = make_float4(o[4], o[5], o[6], o[7]);
    }
}

// ---------------- 5. con_adj = emb @ emb.T (symmetric, conflict-free LDS) ----------------
__global__ __launch_bounds__(256) void syrk_kernel(float* __restrict__ out) {
    const int bi = blockIdx.y, bj = blockIdx.x;
    if (bj < bi) return;

    __shared__ __align__(16) float As[16][132];
    __shared__ __align__(16) float Bs[16][132];
    const int i0 = bi * 128;
    const int j0 = bj * 128;
    const int tid = threadIdx.x;
    const int tx = tid & 15, ty = tid >> 4;
    // thread rows: ty*4..+3 and 64+ty*4..+3;  cols: tx*4..+3 and 64+tx*4..+3

    ull acc2[8][4];
#pragma unroll
    for (int i = 0; i < 8; i++)
#pragma unroll
        for (int j = 0; j < 4; j++) acc2[i][j] = 0ull;

    const float4* E4 = (const float4*)g_emb;

    for (int kk = 0; kk < IN_DIM; kk += 16) {
#pragma unroll
        for (int e = 0; e < 2; e++) {
            int f = tid + e * 256;
            int row = f >> 2, cq = f & 3;
            float4 va = E4[(size_t)(i0 + row) * 32 + (kk >> 2) + cq];
            As[cq * 4 + 0][row] = va.x;
            As[cq * 4 + 1][row] = va.y;
            As[cq * 4 + 2][row] = va.z;
            As[cq * 4 + 3][row] = va.w;
            float4 vb = E4[(size_t)(j0 + row) * 32 + (kk >> 2) + cq];
            Bs[cq * 4 + 0][row] = vb.x;
            Bs[cq * 4 + 1][row] = vb.y;
            Bs[cq * 4 + 2][row] = vb.z;
            Bs[cq * 4 + 3][row] = vb.w;
        }
        __syncthreads();

#pragma unroll 4
        for (int k = 0; k < 16; k++) {
            float4 a0 = *(const float4*)&As[k][ty * 4];
            float4 a1 = *(const float4*)&As[k][64 + ty * 4];
            ulonglong2 bl0 = *(const ulonglong2*)&Bs[k][tx * 4];
            ulonglong2 bl1 = *(const ulonglong2*)&Bs[k][64 + tx * 4];
            float av[8] = {a0.x, a0.y, a0.z, a0.w, a1.x, a1.y, a1.z, a1.w};
#pragma unroll
            for (int i = 0; i < 8; i++) {
                ull ap = pack2(av[i], av[i]);
                ffma2(acc2[i][0], ap, bl0.x);
                ffma2(acc2[i][1], ap, bl0.y);
                ffma2(acc2[i][2], ap, bl1.x);
                ffma2(acc2[i][3], ap, bl1.y);
            }
        }
        __syncthreads();
    }

    float acc[8][8];
#pragma unroll
    for (int i = 0; i < 8; i++)
#pragma unroll
        for (int j4 = 0; j4 < 4; j4++) {
            float2 v = unpack2(acc2[i][j4]);
            acc[i][j4 * 2] = v.x;
            acc[i][j4 * 2 + 1] = v.y;
        }

    // normal tile
#pragma unroll
    for (int i = 0; i < 8; i++) {
        int ri = (i < 4) ? (ty * 4 + i) : (64 + ty * 4 + i - 4);
        float* orow = out + (size_t)(i0 + ri) * NROWS;
        *(float4*)&orow[j0 + tx * 4] = make_float4(acc[i][0], acc[i][1], acc[i][2], acc[i][3]);
        *(float4*)&orow[j0 + 64 + tx * 4] = make_float4(acc[i][4], acc[i][5], acc[i][6], acc[i][7]);
    }
    // mirror tile
    if (bi != bj) {
#pragma unroll
        for (int j = 0; j < 8; j++) {
            int rj = (j < 4) ? (tx * 4 + j) : (64 + tx * 4 + j - 4);
            float* orow = out + (size_t)(j0 + rj) * NROWS;
            *(float4*)&orow[i0 + ty * 4] = make_float4(acc[0][j], acc[1][j], acc[2][j], acc[3][j]);
            *(float4*)&orow[i0 + 64 + ty * 4] = make_float4(acc[4][j], acc[5][j], acc[6][j], acc[7][j]);
        }
    }
}

// ---------------- 6. encoder: gates = x @ enc_W_ih.T, LSTM fused ----------------
__global__ __launch_bounds__(256) void enc_fused(const float* __restrict__ x,
                                                 const float* __restrict__ W,
                                                 const float* __restrict__ b_ih,
                                                 const float* __restrict__ b_hh) {
    __shared__ float As[16][128];
    __shared__ float Ws[16][257];
    __shared__ float gsm[16][256];
    const int i0 = blockIdx.x * 16;
    const int tid = threadIdx.x;
    const int n = tid;

    for (int idx = tid; idx < 16 * 128; idx += 256)
        As[idx >> 7][idx & 127] = x[(size_t)(i0 + (idx >> 7)) * 128 + (idx & 127)];

    float acc[16];
#pragma unroll
    for (int r = 0; r < 16; r++) acc[r] = 0.f;

    for (int kt = 0; kt < 128; kt += 16) {
        __syncthreads();
        for (int f = tid; f < 16 * 256; f += 256) {
            int n2 = f >> 4, kk = f & 15;
            Ws[kk][n2] = W[(size_t)n2 * 128 + kt + kk];
        }
        __syncthreads();
#pragma unroll
        for (int kk = 0; kk < 16; kk++) {
            float b = Ws[kk][n];
#pragma unroll
            for (int r = 0; r < 16; r++) acc[r] += As[r][kt + kk] * b;
        }
    }
    __syncthreads();
#pragma unroll
    for (int r = 0; r < 16; r++) gsm[r][n] = acc[r];
    __syncthreads();

#pragma unroll
    for (int e = 0; e < 4; e++) {
        int idx = tid + e * 256;
        int row = idx >> 6, hh = idx & 63;
        float gi = gsm[row][hh] + b_ih[hh] + b_hh[hh];
        float gg = gsm[row][128 + hh] + b_ih[128 + hh] + b_hh[128 + hh];
        float go = gsm[row][192 + hh] + b_ih[192 + hh] + b_hh[192 + hh];
        float c = sigmoidf_(gi) * tanhf(gg);
        g_henc[(size_t)(i0 + row) * 64 + hh] = sigmoidf_(go) * tanhf(c);
    }
}

// ---------------- 7. decoder: gates = h_enc @ dec_W_ih.T, LSTM fused ----------------
__global__ __launch_bounds__(512) void dec_fused(const float* __restrict__ W,
                                                 const float* __restrict__ b_ih,
                                                 const float* __restrict__ b_hh,
                                                 float* __restrict__ out) {
    __shared__ union {
        struct { float As[16][64]; float Ws[16][513]; } in;
        float gsm[16][512];
    } sm;
    const int i0 = blockIdx.x * 16;
    const int tid = threadIdx.x;
    const int n = tid;

    for (int idx = tid; idx < 16 * 64; idx += 512)
        sm.in.As[idx >> 6][idx & 63] = g_henc[(size_t)(i0 + (idx >> 6)) * 64 + (idx & 63)];

    float acc[16];
#pragma unroll
    for (int r = 0; r < 16; r++) acc[r] = 0.f;

    for (int kt = 0; kt < 64; kt += 16) {
        __syncthreads();
        for (int f = tid; f < 16 * 512; f += 512) {
            int n2 = f >> 4, kk = f & 15;
            sm.in.Ws[kk][n2] = W[(size_t)n2 * 64 + kt + kk];
        }
        __syncthreads();
#pragma unroll
        for (int kk = 0; kk < 16; kk++) {
            float b = sm.in.Ws[kk][n];
#pragma unroll
            for (int r = 0; r < 16; r++) acc[r] += sm.in.As[r][kt + kk] * b;
        }
    }
    __syncthreads();
#pragma unroll
    for (int r = 0; r < 16; r++) sm.gsm[r][n] = acc[r];
    __syncthreads();

#pragma unroll
    for (int e = 0; e < 4; e++) {
        int idx = tid + e * 512;
        int row = idx >> 7, hh = idx & 127;
        float gi = sm.gsm[row][hh] + b_ih[hh] + b_hh[hh];
        float gg = sm.gsm[row][256 + hh] + b_ih[256 + hh] + b_hh[256 + hh];
        float go = sm.gsm[row][384 + hh] + b_ih[384 + hh] + b_hh[384 + hh];
        float c = sigmoidf_(gi) * tanhf(gg);
        out[(size_t)(i0 + row) * 128 + hh] = sigmoidf_(go) * tanhf(c);
    }
}

// ---------------- launch ----------------
extern "C" void kernel_launch(void* const* d_in, const int* in_sizes, int n_in,
                              void* d_out, int out_size) {
    const float* x = (const float*)d_in[0];
    const float* adj = (const float*)d_in[1];
    const float* fea_W = (const float*)d_in[2];
    const float* fea_b = (const float*)d_in[3];
    const float* gat_W = (const float*)d_in[4];
    const float* gat_a = (const float*)d_in[5];
    const float* enc_W_ih = (const float*)d_in[6];
    const float* enc_b_ih = (const float*)d_in[8];
    const float* enc_b_hh = (const float*)d_in[9];
    const float* dec_W_ih = (const float*)d_in[10];
    const float* dec_b_ih = (const float*)d_in[12];
    const float* dec_b_hh = (const float*)d_in[13];

    float* out = (float*)d_out;
    float* con_adj = out;
    float* att_adj = out + (size_t)NROWS * NROWS;

    struct_kernel<<<NROWS / 16, 256>>>(x, fea_W, fea_b);           // 1
    wh_s1s2_kernel<<<NROWS / 16, 256>>>(gat_W, gat_a);             // 2
    vec_kernel<<<NROWS / 256, 256>>>();                            // 3
    attn_emb_kernel<<<NROWS / 32, 128>>>(adj);                     // 4  <- ncu capture slot
    syrk_kernel<<<dim3(64, 64), 256>>>(con_adj);                   // 5
    enc_fused<<<NROWS / 16, 256>>>(x, enc_W_ih, enc_b_ih, enc_b_hh);  // 6
    dec_fused<<<NROWS / 16, 512>>>(dec_W_ih, dec_b_ih, dec_b_hh, att_adj);  // 7
}

// round 5
// speedup vs baseline: 1.8246x; 1.2894x over previous
#include <cuda_runtime.h>
#include <cuda_bf16.h>
#include <cstdint>

#define NROWS 8192
#define IN_DIM 128
#define HID 64
#define NSPLIT 8
#define JSEG (NROWS / NSPLIT)

// ---------------- scratch (static device globals; no allocation) ----------------
__device__ __align__(16) float g_struct[NROWS * HID];
__device__ __align__(16) float g_Wh[NROWS * IN_DIM];
__device__ __align__(16) float g_s1[NROWS];
__device__ __align__(16) float g_s2[NROWS];
__device__ __align__(16) float g_A[NROWS];
__device__ __align__(16) float g_B[NROWS];
__device__ __align__(16) float g_C[NROWS];
__device__ __align__(16) float g_D[NROWS];
__device__ unsigned g_s2max_bits = 0u;   // atomicMax idempotent -> replay-deterministic
__device__ __align__(16) float g_henc[NROWS * HID];
__device__ __align__(16) float g_emb[NROWS * IN_DIM];
__device__ __align__(16) float g_pacc[NSPLIT * NROWS * IN_DIM];  // partial attn accumulators
__device__ __align__(16) float g_pden[NSPLIT * NROWS];           // partial denominators

// ---------------- helpers ----------------
__device__ __forceinline__ float sigmoidf_(float x) { return 1.0f / (1.0f + __expf(-x)); }

__device__ __forceinline__ unsigned float_key(float f) {
    unsigned b = __float_as_uint(f);
    return (b & 0x80000000u) ? ~b : (b | 0x80000000u);
}
__device__ __forceinline__ float key_float(unsigned k) {
    unsigned b = (k & 0x80000000u) ? (k & 0x7fffffffu) : ~k;
    return __uint_as_float(b);
}

typedef unsigned long long ull;
__device__ __forceinline__ ull pack2(float lo, float hi) {
    ull r;
    asm("mov.b64 %0, {%1, %2};" : "=l"(r) : "f"(lo), "f"(hi));
    return r;
}
__device__ __forceinline__ void ffma2(ull& d, ull a, ull b) {
    asm("fma.rn.f32x2 %0, %1, %2, %3;" : "=l"(d) : "l"(a), "l"(b), "l"(d));
}
__device__ __forceinline__ float2 unpack2(ull v) {
    float2 r;
    asm("mov.b64 {%0, %1}, %2;" : "=f"(r.x), "=f"(r.y) : "l"(v));
    return r;
}

// ---------------- 1. structure = relu(x @ fea_W + fea_b) ----------------
__global__ __launch_bounds__(256) void struct_kernel(const float* __restrict__ A,
                                                     const float* __restrict__ W,
                                                     const float* __restrict__ bias) {
    __shared__ float As[16][128];
    const int i0 = blockIdx.x * 16;
    const int tid = threadIdx.x;
    const int n = tid & 63, rg = tid >> 6;

    for (int idx = tid; idx < 16 * 128; idx += 256)
        As[idx >> 7][idx & 127] = A[(size_t)(i0 + (idx >> 7)) * 128 + (idx & 127)];
    __syncthreads();

    float acc[4] = {0.f, 0.f, 0.f, 0.f};
#pragma unroll 4
    for (int k = 0; k < 128; k++) {
        float b = W[(size_t)k * 64 + n];
#pragma unroll
        for (int r = 0; r < 4; r++) acc[r] += As[rg * 4 + r][k] * b;
    }
    float bv = bias[n];
#pragma unroll
    for (int r = 0; r < 4; r++)
        g_struct[(size_t)(i0 + rg * 4 + r) * 64 + n] = fmaxf(acc[r] + bv, 0.f);
}

// ---------------- 2. Wh = structure @ gat_W, fused s1/s2/max(s2) ----------------
__global__ __launch_bounds__(256) void wh_s1s2_kernel(const float* __restrict__ W,
                                                      const float* __restrict__ gat_a) {
    __shared__ float As[16][64];
    __shared__ float r1[8][8], r2[8][8];
    const int i0 = blockIdx.x * 16;
    const int tid = threadIdx.x;
    const int n = tid & 127, rg = tid >> 7;

    for (int idx = tid; idx < 16 * 64; idx += 256)
        As[idx >> 6][idx & 63] = g_struct[(size_t)(i0 + (idx >> 6)) * 64 + (idx & 63)];
    __syncthreads();

    float acc[8];
#pragma unroll
    for (int r = 0; r < 8; r++) acc[r] = 0.f;
#pragma unroll 4
    for (int k = 0; k < 64; k++) {
        float b = W[(size_t)k * 128 + n];
#pragma unroll
        for (int r = 0; r < 8; r++) acc[r] += As[rg * 8 + r][k] * b;
    }
#pragma unroll
    for (int r = 0; r < 8; r++)
        g_Wh[(size_t)(i0 + rg * 8 + r) * 128 + n] = acc[r];

    float a1v = gat_a[n], a2v = gat_a[128 + n];
    int warp = tid >> 5, lane = tid & 31;
#pragma unroll
    for (int r = 0; r < 8; r++) {
        float v1 = acc[r] * a1v, v2 = acc[r] * a2v;
#pragma unroll
        for (int off = 16; off; off >>= 1) {
            v1 += __shfl_xor_sync(0xffffffffu, v1, off);
            v2 += __shfl_xor_sync(0xffffffffu, v2, off);
        }
        if (lane == 0) { r1[warp][r] = v1; r2[warp][r] = v2; }
    }
    __syncthreads();
    if (tid < 16) {
        int rgg = tid >> 3, rr = tid & 7;
        float s1 = r1[rgg * 4 + 0][rr] + r1[rgg * 4 + 1][rr] + r1[rgg * 4 + 2][rr] + r1[rgg * 4 + 3][rr];
        float s2 = r2[rgg * 4 + 0][rr] + r2[rgg * 4 + 1][rr] + r2[rgg * 4 + 2][rr] + r2[rgg * 4 + 3][rr];
        g_s1[i0 + tid] = s1;
        g_s2[i0 + tid] = s2;
        float m = s2;
#pragma unroll
        for (int off = 8; off; off >>= 1) m = fmaxf(m, __shfl_xor_sync(0x0000ffffu, m, off));
        if (tid == 0) atomicMax(&g_s2max_bits, float_key(m));
    }
}

// ---------------- 3. precompute A,B,C,D ----------------
__global__ void vec_kernel() {
    int i = blockIdx.x * 256 + threadIdx.x;
    float s2max = key_float(g_s2max_bits);
    float t = g_s1[i] + s2max;
    float m = t > 0.f ? t : 0.2f * t;
    g_A[i] = expf(t - m);
    g_C[i] = expf(0.2f * t - m);
    float u = g_s2[i] - s2max;
    g_B[i] = expf(u);
    g_D[i] = expf(0.2f * u);
}

// ---------------- 4. attention partial: p(32 x JSEG) @ Wh(JSEG x 128) -> scratch ----------------
// grid (256, NSPLIT); block 128 threads; thread 4 rows x 8 cols; FFMA2; j-segment partial sums.
__global__ __launch_bounds__(128) void attn_partial_kernel(const float* __restrict__ adj) {
    __shared__ float p_s[32 * 36];
    __shared__ __align__(16) float wh_s[32 * 128];
    __shared__ float s1_s[32], A_s[32], C_s[32];

    const int i0 = blockIdx.x * 32;
    const int js = blockIdx.y;
    const int jb = js * JSEG;
    const int tid = threadIdx.x;
    if (tid < 32) {
        s1_s[tid] = g_s1[i0 + tid];
        A_s[tid] = g_A[i0 + tid];
        C_s[tid] = g_C[i0 + tid];
    }

    const int cg = tid & 15;
    const int rg = tid >> 4;
    const int c4 = (tid & 7) * 4;
    const int rp = tid >> 3;

    ull acc[4][4];
#pragma unroll
    for (int a = 0; a < 4; a++)
#pragma unroll
        for (int b = 0; b < 4; b++) acc[a][b] = 0ull;
    float dsum0 = 0.f, dsum1 = 0.f;

    const float4* Wh4 = (const float4*)g_Wh;
    const float4* S24 = (const float4*)g_s2;
    const float4* B4 = (const float4*)g_B;
    const float4* D4 = (const float4*)g_D;

    for (int jc = jb; jc < jb + JSEG; jc += 32) {
        __syncthreads();

#pragma unroll
        for (int e = 0; e < 8; e++) {
            int idx = tid + e * 128;
            int k = idx >> 5, q = idx & 31;
            ((float4*)wh_s)[k * 32 + q] = Wh4[(size_t)(jc + k) * 32 + q];
        }

        {
            float4 s2v = S24[(jc >> 2) + (tid & 7)];
            float4 Bv = B4[(jc >> 2) + (tid & 7)];
            float4 Dv = D4[(jc >> 2) + (tid & 7)];
#pragma unroll
            for (int rr = 0; rr < 2; rr++) {
                int r = rp * 2 + rr;
                float4 av = *(const float4*)&adj[(size_t)(i0 + r) * NROWS + jc + c4];
                float s1 = s1_s[r], Av = A_s[r], Cv = C_s[r];
                float4 pv;
                { float t = s1 + s2v.x; pv.x = (av.x > 0.f) ? (t > 0.f ? Av * Bv.x : Cv * Dv.x) : 0.f; }
                { float t = s1 + s2v.y; pv.y = (av.y > 0.f) ? (t > 0.f ? Av * Bv.y : Cv * Dv.y) : 0.f; }
                { float t = s1 + s2v.z; pv.z = (av.z > 0.f) ? (t > 0.f ? Av * Bv.z : Cv * Dv.z) : 0.f; }
                { float t = s1 + s2v.w; pv.w = (av.w > 0.f) ? (t > 0.f ? Av * Bv.w : Cv * Dv.w) : 0.f; }
                *(float4*)&p_s[r * 36 + c4] = pv;
                float s = (pv.x + pv.y) + (pv.z + pv.w);
                if (rr == 0) dsum0 += s; else dsum1 += s;
            }
        }
        __syncthreads();

#pragma unroll 8
        for (int k = 0; k < 32; k++) {
            ulonglong2 b0 = *(const ulonglong2*)&wh_s[k * 128 + cg * 4];
            ulonglong2 b1 = *(const ulonglong2*)&wh_s[k * 128 + 64 + cg * 4];
#pragma unroll
            for (int rr = 0; rr < 4; rr++) {
                float p = p_s[(rg * 4 + rr) * 36 + k];
                ull pp = pack2(p, p);
                ffma2(acc[rr][0], pp, b0.x);
                ffma2(acc[rr][1], pp, b0.y);
                ffma2(acc[rr][2], pp, b1.x);
                ffma2(acc[rr][3], pp, b1.y);
            }
        }
    }

    // partial denominators: 8 lanes per row-pair
#pragma unroll
    for (int off = 4; off; off >>= 1) {
        dsum0 += __shfl_down_sync(0xffffffffu, dsum0, off, 8);
        dsum1 += __shfl_down_sync(0xffffffffu, dsum1, off, 8);
    }
    if ((tid & 7) == 0) {
        g_pden[(size_t)js * NROWS + i0 + rp * 2] = dsum0;
        g_pden[(size_t)js * NROWS + i0 + rp * 2 + 1] = dsum1;
    }

    // partial accumulators
    float* pa = g_pacc + (size_t)js * NROWS * IN_DIM;
#pragma unroll
    for (int rr = 0; rr < 4; rr++) {
        int r = rg * 4 + rr;
        float2 v0 = unpack2(acc[rr][0]), v1 = unpack2(acc[rr][1]);
        float2 v2 = unpack2(acc[rr][2]), v3 = unpack2(acc[rr][3]);
        *(float4*)&pa[(size_t)(i0 + r) * IN_DIM + cg * 4] = make_float4(v0.x, v0.y, v1.x, v1.y);
        *(float4*)&pa[(size_t)(i0 + r) * IN_DIM + 64 + cg * 4] = make_float4(v2.x, v2.y, v3.x, v3.y);
    }
}

// ---------------- 4b. combine partials: emb = elu(sum(acc)/sum(den)) ----------------
__global__ __launch_bounds__(256) void combine_kernel() {
    int idx = blockIdx.x * 256 + threadIdx.x;        // 0 .. NROWS*32-1 (float4 granularity)
    int row = idx >> 5;
    float den = 0.f;
    float4 acc = make_float4(0.f, 0.f, 0.f, 0.f);
#pragma unroll
    for (int s = 0; s < NSPLIT; s++) {
        den += g_pden[(size_t)s * NROWS + row];
        float4 v = ((const float4*)g_pacc)[(size_t)s * NROWS * 32 + idx];
        acc.x += v.x; acc.y += v.y; acc.z += v.z; acc.w += v.w;
    }
    float inv = 1.0f / den;
    float o[4] = {acc.x * inv, acc.y * inv, acc.z * inv, acc.w * inv};
#pragma unroll
    for (int j = 0; j < 4; j++) o[j] = o[j] > 0.f ? o[j] : expm1f(o[j]);
    ((float4*)g_emb)[idx] = make_float4(o[0], o[1], o[2], o[3]);
}

// ---------------- 5. con_adj = emb @ emb.T (symmetric, conflict-free LDS) ----------------
__global__ __launch_bounds__(256) void syrk_kernel(float* __restrict__ out) {
    const int bi = blockIdx.y, bj = blockIdx.x;
    if (bj < bi) return;

    __shared__ __align__(16) float As[16][132];
    __shared__ __align__(16) float Bs[16][132];
    const int i0 = bi * 128;
    const int j0 = bj * 128;
    const int tid = threadIdx.x;
    const int tx = tid & 15, ty = tid >> 4;

    ull acc2[8][4];
#pragma unroll
    for (int i = 0; i < 8; i++)
#pragma unroll
        for (int j = 0; j < 4; j++) acc2[i][j] = 0ull;

    const float4* E4 = (const float4*)g_emb;

    for (int kk = 0; kk < IN_DIM; kk += 16) {
#pragma unroll
        for (int e = 0; e < 2; e++) {
            int f = tid + e * 256;
            int row = f >> 2, cq = f & 3;
            float4 va = E4[(size_t)(i0 + row) * 32 + (kk >> 2) + cq];
            As[cq * 4 + 0][row] = va.x;
            As[cq * 4 + 1][row] = va.y;
            As[cq * 4 + 2][row] = va.z;
            As[cq * 4 + 3][row] = va.w;
            float4 vb = E4[(size_t)(j0 + row) * 32 + (kk >> 2) + cq];
            Bs[cq * 4 + 0][row] = vb.x;
            Bs[cq * 4 + 1][row] = vb.y;
            Bs[cq * 4 + 2][row] = vb.z;
            Bs[cq * 4 + 3][row] = vb.w;
        }
        __syncthreads();

#pragma unroll 4
        for (int k = 0; k < 16; k++) {
            float4 a0 = *(const float4*)&As[k][ty * 4];
            float4 a1 = *(const float4*)&As[k][64 + ty * 4];
            ulonglong2 bl0 = *(const ulonglong2*)&Bs[k][tx * 4];
            ulonglong2 bl1 = *(const ulonglong2*)&Bs[k][64 + tx * 4];
            float av[8] = {a0.x, a0.y, a0.z, a0.w, a1.x, a1.y, a1.z, a1.w};
#pragma unroll
            for (int i = 0; i < 8; i++) {
                ull ap = pack2(av[i], av[i]);
                ffma2(acc2[i][0], ap, bl0.x);
                ffma2(acc2[i][1], ap, bl0.y);
                ffma2(acc2[i][2], ap, bl1.x);
                ffma2(acc2[i][3], ap, bl1.y);
            }
        }
        __syncthreads();
    }

    float acc[8][8];
#pragma unroll
    for (int i = 0; i < 8; i++)
#pragma unroll
        for (int j4 = 0; j4 < 4; j4++) {
            float2 v = unpack2(acc2[i][j4]);
            acc[i][j4 * 2] = v.x;
            acc[i][j4 * 2 + 1] = v.y;
        }

#pragma unroll
    for (int i = 0; i < 8; i++) {
        int ri = (i < 4) ? (ty * 4 + i) : (64 + ty * 4 + i - 4);
        float* orow = out + (size_t)(i0 + ri) * NROWS;
        *(float4*)&orow[j0 + tx * 4] = make_float4(acc[i][0], acc[i][1], acc[i][2], acc[i][3]);
        *(float4*)&orow[j0 + 64 + tx * 4] = make_float4(acc[i][4], acc[i][5], acc[i][6], acc[i][7]);
    }
    if (bi != bj) {
#pragma unroll
        for (int j = 0; j < 8; j++) {
            int rj = (j < 4) ? (tx * 4 + j) : (64 + tx * 4 + j - 4);
            float* orow = out + (size_t)(j0 + rj) * NROWS;
            *(float4*)&orow[i0 + ty * 4] = make_float4(acc[0][j], acc[1][j], acc[2][j], acc[3][j]);
            *(float4*)&orow[i0 + 64 + ty * 4] = make_float4(acc[4][j], acc[5][j], acc[6][j], acc[7][j]);
        }
    }
}

// ---------------- 6. encoder: gates = x @ enc_W_ih.T, LSTM fused ----------------
__global__ __launch_bounds__(256) void enc_fused(const float* __restrict__ x,
                                                 const float* __restrict__ W,
                                                 const float* __restrict__ b_ih,
                                                 const float* __restrict__ b_hh) {
    __shared__ float As[16][128];
    __shared__ float Ws[16][257];
    __shared__ float gsm[16][256];
    const int i0 = blockIdx.x * 16;
    const int tid = threadIdx.x;
    const int n = tid;

    for (int idx = tid; idx < 16 * 128; idx += 256)
        As[idx >> 7][idx & 127] = x[(size_t)(i0 + (idx >> 7)) * 128 + (idx & 127)];

    float acc[16];
#pragma unroll
    for (int r = 0; r < 16; r++) acc[r] = 0.f;

    for (int kt = 0; kt < 128; kt += 16) {
        __syncthreads();
        for (int f = tid; f < 16 * 256; f += 256) {
            int n2 = f >> 4, kk = f & 15;
            Ws[kk][n2] = W[(size_t)n2 * 128 + kt + kk];
        }
        __syncthreads();
#pragma unroll
        for (int kk = 0; kk < 16; kk++) {
            float b = Ws[kk][n];
#pragma unroll
            for (int r = 0; r < 16; r++) acc[r] += As[r][kt + kk] * b;
        }
    }
    __syncthreads();
#pragma unroll
    for (int r = 0; r < 16; r++) gsm[r][n] = acc[r];
    __syncthreads();

#pragma unroll
    for (int e = 0; e < 4; e++) {
        int idx = tid + e * 256;
        int row = idx >> 6, hh = idx & 63;
        float gi = gsm[row][hh] + b_ih[hh] + b_hh[hh];
        float gg = gsm[row][128 + hh] + b_ih[128 + hh] + b_hh[128 + hh];
        float go = gsm[row][192 + hh] + b_ih[192 + hh] + b_hh[192 + hh];
        float c = sigmoidf_(gi) * tanhf(gg);
        g_henc[(size_t)(i0 + row) * 64 + hh] = sigmoidf_(go) * tanhf(c);
    }
}

// ---------------- 7. decoder: gates = h_enc @ dec_W_ih.T, LSTM fused ----------------
__global__ __launch_bounds__(512) void dec_fused(const float* __restrict__ W,
                                                 const float* __restrict__ b_ih,
                                                 const float* __restrict__ b_hh,
                                                 float* __restrict__ out) {
    __shared__ union {
        struct { float As[16][64]; float Ws[16][513]; } in;
        float gsm[16][512];
    } sm;
    const int i0 = blockIdx.x * 16;
    const int tid = threadIdx.x;
    const int n = tid;

    for (int idx = tid; idx < 16 * 64; idx += 512)
        sm.in.As[idx >> 6][idx & 63] = g_henc[(size_t)(i0 + (idx >> 6)) * 64 + (idx & 63)];

    float acc[16];
#pragma unroll
    for (int r = 0; r < 16; r++) acc[r] = 0.f;

    for (int kt = 0; kt < 64; kt += 16) {
        __syncthreads();
        for (int f = tid; f < 16 * 512; f += 512) {
            int n2 = f >> 4, kk = f & 15;
            sm.in.Ws[kk][n2] = W[(size_t)n2 * 64 + kt + kk];
        }
        __syncthreads();
#pragma unroll
        for (int kk = 0; kk < 16; kk++) {
            float b = sm.in.Ws[kk][n];
#pragma unroll
            for (int r = 0; r < 16; r++) acc[r] += sm.in.As[r][kt + kk] * b;
        }
    }
    __syncthreads();
#pragma unroll
    for (int r = 0; r < 16; r++) sm.gsm[r][n] = acc[r];
    __syncthreads();

#pragma unroll
    for (int e = 0; e < 4; e++) {
        int idx = tid + e * 512;
        int row = idx >> 7, hh = idx & 127;
        float gi = sm.gsm[row][hh] + b_ih[hh] + b_hh[hh];
        float gg = sm.gsm[row][256 + hh] + b_ih[256 + hh] + b_hh[256 + hh];
        float go = sm.gsm[row][384 + hh] + b_ih[384 + hh] + b_hh[384 + hh];
        float c = sigmoidf_(gi) * tanhf(gg);
        out[(size_t)(i0 + row) * 128 + hh] = sigmoidf_(go) * tanhf(c);
    }
}

// ---------------- launch ----------------
extern "C" void kernel_launch(void* const* d_in, const int* in_sizes, int n_in,
                              void* d_out, int out_size) {
    const float* x = (const float*)d_in[0];
    const float* adj = (const float*)d_in[1];
    const float* fea_W = (const float*)d_in[2];
    const float* fea_b = (const float*)d_in[3];
    const float* gat_W = (const float*)d_in[4];
    const float* gat_a = (const float*)d_in[5];
    const float* enc_W_ih = (const float*)d_in[6];
    const float* enc_b_ih = (const float*)d_in[8];
    const float* enc_b_hh = (const float*)d_in[9];
    const float* dec_W_ih = (const float*)d_in[10];
    const float* dec_b_ih = (const float*)d_in[12];
    const float* dec_b_hh = (const float*)d_in[13];

    float* out = (float*)d_out;
    float* con_adj = out;
    float* att_adj = out + (size_t)NROWS * NROWS;

    struct_kernel<<<NROWS / 16, 256>>>(x, fea_W, fea_b);                    // 1
    wh_s1s2_kernel<<<NROWS / 16, 256>>>(gat_W, gat_a);                      // 2
    vec_kernel<<<NROWS / 256, 256>>>();                                     // 3
    attn_partial_kernel<<<dim3(NROWS / 32, NSPLIT), 128>>>(adj);            // 4  <- ncu slot
    combine_kernel<<<NROWS * 32 / 256, 256>>>();                            // 5
    syrk_kernel<<<dim3(64, 64), 256>>>(con_adj);                            // 6
    enc_fused<<<NROWS / 16, 256>>>(x, enc_W_ih, enc_b_ih, enc_b_hh);        // 7
    dec_fused<<<NROWS / 16, 512>>>(dec_W_ih, dec_b_ih, dec_b_hh, att_adj);  // 8
}

// round 6
// speedup vs baseline: 1.9196x; 1.0521x over previous
#include <cuda_runtime.h>
#include <cuda_bf16.h>
#include <cstdint>

#define NROWS 8192
#define IN_DIM 128
#define HID 64
#define NSPLIT 16
#define JSEG (NROWS / NSPLIT)

// ---------------- scratch (static device globals; no allocation) ----------------
__device__ __align__(16) float g_struct[NROWS * HID];
__device__ __align__(16) float g_Wh[NROWS * IN_DIM];
__device__ __align__(16) float g_s1[NROWS];
__device__ __align__(16) float g_s2[NROWS];
__device__ __align__(16) float g_A[NROWS];
__device__ __align__(16) float g_B[NROWS];
__device__ __align__(16) float g_C[NROWS];
__device__ __align__(16) float g_D[NROWS];
__device__ unsigned g_s2max_bits = 0u;   // atomicMax idempotent -> replay-deterministic
__device__ __align__(16) float g_henc[NROWS * HID];
__device__ __align__(16) float g_emb[NROWS * IN_DIM];
__device__ __align__(16) float g_pacc[NSPLIT * NROWS * IN_DIM];
__device__ __align__(16) float g_pden[NSPLIT * NROWS];

// ---------------- helpers ----------------
__device__ __forceinline__ float sigmoidf_(float x) { return 1.0f / (1.0f + __expf(-x)); }

__device__ __forceinline__ unsigned float_key(float f) {
    unsigned b = __float_as_uint(f);
    return (b & 0x80000000u) ? ~b : (b | 0x80000000u);
}
__device__ __forceinline__ float key_float(unsigned k) {
    unsigned b = (k & 0x80000000u) ? (k & 0x7fffffffu) : ~k;
    return __uint_as_float(b);
}

typedef unsigned long long ull;
__device__ __forceinline__ ull pack2(float lo, float hi) {
    ull r;
    asm("mov.b64 %0, {%1, %2};" : "=l"(r) : "f"(lo), "f"(hi));
    return r;
}
__device__ __forceinline__ void ffma2(ull& d, ull a, ull b) {
    asm("fma.rn.f32x2 %0, %1, %2, %3;" : "=l"(d) : "l"(a), "l"(b), "l"(d));
}
__device__ __forceinline__ float2 unpack2(ull v) {
    float2 r;
    asm("mov.b64 {%0, %1}, %2;" : "=f"(r.x), "=f"(r.y) : "l"(v));
    return r;
}

// ---------------- 1. structure = relu(x @ fea_W + fea_b) ----------------
__global__ __launch_bounds__(256) void struct_kernel(const float* __restrict__ A,
                                                     const float* __restrict__ W,
                                                     const float* __restrict__ bias) {
    __shared__ float As[16][128];
    const int i0 = blockIdx.x * 16;
    const int tid = threadIdx.x;
    const int n = tid & 63, rg = tid >> 6;

    for (int idx = tid; idx < 16 * 128; idx += 256)
        As[idx >> 7][idx & 127] = A[(size_t)(i0 + (idx >> 7)) * 128 + (idx & 127)];
    __syncthreads();

    float acc[4] = {0.f, 0.f, 0.f, 0.f};
#pragma unroll 4
    for (int k = 0; k < 128; k++) {
        float b = W[(size_t)k * 64 + n];
#pragma unroll
        for (int r = 0; r < 4; r++) acc[r] += As[rg * 4 + r][k] * b;
    }
    float bv = bias[n];
#pragma unroll
    for (int r = 0; r < 4; r++)
        g_struct[(size_t)(i0 + rg * 4 + r) * 64 + n] = fmaxf(acc[r] + bv, 0.f);
}

// ---------------- 2. Wh = structure @ gat_W, fused s1/s2/max(s2) ----------------
__global__ __launch_bounds__(256) void wh_s1s2_kernel(const float* __restrict__ W,
                                                      const float* __restrict__ gat_a) {
    __shared__ float As[16][64];
    __shared__ float r1[8][8], r2[8][8];
    const int i0 = blockIdx.x * 16;
    const int tid = threadIdx.x;
    const int n = tid & 127, rg = tid >> 7;

    for (int idx = tid; idx < 16 * 64; idx += 256)
        As[idx >> 6][idx & 63] = g_struct[(size_t)(i0 + (idx >> 6)) * 64 + (idx & 63)];
    __syncthreads();

    float acc[8];
#pragma unroll
    for (int r = 0; r < 8; r++) acc[r] = 0.f;
#pragma unroll 4
    for (int k = 0; k < 64; k++) {
        float b = W[(size_t)k * 128 + n];
#pragma unroll
        for (int r = 0; r < 8; r++) acc[r] += As[rg * 8 + r][k] * b;
    }
#pragma unroll
    for (int r = 0; r < 8; r++)
        g_Wh[(size_t)(i0 + rg * 8 + r) * 128 + n] = acc[r];

    float a1v = gat_a[n], a2v = gat_a[128 + n];
    int warp = tid >> 5, lane = tid & 31;
#pragma unroll
    for (int r = 0; r < 8; r++) {
        float v1 = acc[r] * a1v, v2 = acc[r] * a2v;
#pragma unroll
        for (int off = 16; off; off >>= 1) {
            v1 += __shfl_xor_sync(0xffffffffu, v1, off);
            v2 += __shfl_xor_sync(0xffffffffu, v2, off);
        }
        if (lane == 0) { r1[warp][r] = v1; r2[warp][r] = v2; }
    }
    __syncthreads();
    if (tid < 16) {
        int rgg = tid >> 3, rr = tid & 7;
        float s1 = r1[rgg * 4 + 0][rr] + r1[rgg * 4 + 1][rr] + r1[rgg * 4 + 2][rr] + r1[rgg * 4 + 3][rr];
        float s2 = r2[rgg * 4 + 0][rr] + r2[rgg * 4 + 1][rr] + r2[rgg * 4 + 2][rr] + r2[rgg * 4 + 3][rr];
        g_s1[i0 + tid] = s1;
        g_s2[i0 + tid] = s2;
        float m = s2;
#pragma unroll
        for (int off = 8; off; off >>= 1) m = fmaxf(m, __shfl_xor_sync(0x0000ffffu, m, off));
        if (tid == 0) atomicMax(&g_s2max_bits, float_key(m));
    }
}

// ---------------- 3. precompute A,B,C,D ----------------
__global__ void vec_kernel() {
    int i = blockIdx.x * 256 + threadIdx.x;
    float s2max = key_float(g_s2max_bits);
    float t = g_s1[i] + s2max;
    float m = t > 0.f ? t : 0.2f * t;
    g_A[i] = expf(t - m);
    g_C[i] = expf(0.2f * t - m);
    float u = g_s2[i] - s2max;
    g_B[i] = expf(u);
    g_D[i] = expf(0.2f * u);
}

// ---------------- 4. attention partial: block tile 64x128, thread 8x8, LDS.64 p-pairs ----------------
__global__ __launch_bounds__(128, 4) void attn_partial_kernel(const float* __restrict__ adj) {
    __shared__ __align__(16) float p_s[64 * 36];     // [r][k] stride 36 (float4 & 8B pair aligned)
    __shared__ __align__(16) float wh_s[32 * 128];   // [k][c]
    __shared__ float s1_s[64], A_s[64], C_s[64];

    const int i0 = blockIdx.x * 64;
    const int jb = blockIdx.y * JSEG;
    const int tid = threadIdx.x;
    if (tid < 64) {
        s1_s[tid] = g_s1[i0 + tid];
        A_s[tid] = g_A[i0 + tid];
        C_s[tid] = g_C[i0 + tid];
    }

    const int tx = tid & 15;        // GEMM col group: cols tx*4..+3, 64+tx*4..+3
    const int ry = tid >> 4;        // GEMM row group: rows ry*8..ry*8+7
    const int c4 = (tid & 7) * 4;   // build cols
    const int rp = tid >> 3;        // build rows rp*4..rp*4+3

    ull acc[8][4];
#pragma unroll
    for (int a = 0; a < 8; a++)
#pragma unroll
        for (int b = 0; b < 4; b++) acc[a][b] = 0ull;
    float dsum[4] = {0.f, 0.f, 0.f, 0.f};

    const float4* Wh4 = (const float4*)g_Wh;
    const float4* S24 = (const float4*)g_s2;
    const float4* B4 = (const float4*)g_B;
    const float4* D4 = (const float4*)g_D;

    for (int jc = jb; jc < jb + JSEG; jc += 32) {
        __syncthreads();

        // Wh tile: 32 k-rows x 128 cols (1024 float4, 8 per thread)
#pragma unroll
        for (int e = 0; e < 8; e++) {
            int idx = tid + e * 128;
            int k = idx >> 5, q = idx & 31;
            ((float4*)wh_s)[k * 32 + q] = Wh4[(size_t)(jc + k) * 32 + q];
        }

        // p tile 64x32: each thread 4 rows x 4 cols, factorized exp
        {
            float4 s2v = S24[(jc >> 2) + (tid & 7)];
            float4 Bv = B4[(jc >> 2) + (tid & 7)];
            float4 Dv = D4[(jc >> 2) + (tid & 7)];
#pragma unroll
            for (int rr = 0; rr < 4; rr++) {
                int r = rp * 4 + rr;
                float4 av = *(const float4*)&adj[(size_t)(i0 + r) * NROWS + jc + c4];
                float s1 = s1_s[r], Av = A_s[r], Cv = C_s[r];
                float4 pv;
                { float t = s1 + s2v.x; pv.x = (av.x > 0.f) ? (t > 0.f ? Av * Bv.x : Cv * Dv.x) : 0.f; }
                { float t = s1 + s2v.y; pv.y = (av.y > 0.f) ? (t > 0.f ? Av * Bv.y : Cv * Dv.y) : 0.f; }
                { float t = s1 + s2v.z; pv.z = (av.z > 0.f) ? (t > 0.f ? Av * Bv.z : Cv * Dv.z) : 0.f; }
                { float t = s1 + s2v.w; pv.w = (av.w > 0.f) ? (t > 0.f ? Av * Bv.w : Cv * Dv.w) : 0.f; }
                *(float4*)&p_s[r * 36 + c4] = pv;
                dsum[rr] += (pv.x + pv.y) + (pv.z + pv.w);
            }
        }
        __syncthreads();

        // acc += p(64x32) @ wh(32x128); k in pairs; LDS.64 p, LDS.128 b
#pragma unroll 4
        for (int k = 0; k < 32; k += 2) {
            ulonglong2 b0a = *(const ulonglong2*)&wh_s[k * 128 + tx * 4];
            ulonglong2 b1a = *(const ulonglong2*)&wh_s[k * 128 + 64 + tx * 4];
            ulonglong2 b0b = *(const ulonglong2*)&wh_s[(k + 1) * 128 + tx * 4];
            ulonglong2 b1b = *(const ulonglong2*)&wh_s[(k + 1) * 128 + 64 + tx * 4];
#pragma unroll
            for (int r = 0; r < 8; r++) {
                float2 p2 = *(const float2*)&p_s[(ry * 8 + r) * 36 + k];   // LDS.64
                ull pa = pack2(p2.x, p2.x);
                ull pb = pack2(p2.y, p2.y);
                ffma2(acc[r][0], pa, b0a.x);
                ffma2(acc[r][1], pa, b0a.y);
                ffma2(acc[r][2], pa, b1a.x);
                ffma2(acc[r][3], pa, b1a.y);
                ffma2(acc[r][0], pb, b0b.x);
                ffma2(acc[r][1], pb, b0b.y);
                ffma2(acc[r][2], pb, b1b.x);
                ffma2(acc[r][3], pb, b1b.y);
            }
        }
    }

    // partial denominators: reduce across 8 lanes (tid&7), rows rp*4..+3
#pragma unroll
    for (int off = 4; off; off >>= 1) {
#pragma unroll
        for (int rr = 0; rr < 4; rr++)
            dsum[rr] += __shfl_down_sync(0xffffffffu, dsum[rr], off, 8);
    }
    if ((tid & 7) == 0) {
#pragma unroll
        for (int rr = 0; rr < 4; rr++)
            g_pden[(size_t)blockIdx.y * NROWS + i0 + rp * 4 + rr] = dsum[rr];
    }

    // partial accumulators
    float* pa = g_pacc + (size_t)blockIdx.y * NROWS * IN_DIM;
#pragma unroll
    for (int r = 0; r < 8; r++) {
        int row = i0 + ry * 8 + r;
        float2 v0 = unpack2(acc[r][0]), v1 = unpack2(acc[r][1]);
        float2 v2 = unpack2(acc[r][2]), v3 = unpack2(acc[r][3]);
        *(float4*)&pa[(size_t)row * IN_DIM + tx * 4] = make_float4(v0.x, v0.y, v1.x, v1.y);
        *(float4*)&pa[(size_t)row * IN_DIM + 64 + tx * 4] = make_float4(v2.x, v2.y, v3.x, v3.y);
    }
}

// ---------------- 4b. combine partials: emb = elu(sum(acc)/sum(den)) ----------------
__global__ __launch_bounds__(256) void combine_kernel() {
    int idx = blockIdx.x * 256 + threadIdx.x;        // float4 granularity
    int row = idx >> 5;
    float den = 0.f;
    float4 acc = make_float4(0.f, 0.f, 0.f, 0.f);
#pragma unroll
    for (int s = 0; s < NSPLIT; s++) {
        den += g_pden[(size_t)s * NROWS + row];
        float4 v = ((const float4*)g_pacc)[(size_t)s * NROWS * 32 + idx];
        acc.x += v.x; acc.y += v.y; acc.z += v.z; acc.w += v.w;
    }
    float inv = 1.0f / den;
    float o[4] = {acc.x * inv, acc.y * inv, acc.z * inv, acc.w * inv};
#pragma unroll
    for (int j = 0; j < 4; j++) o[j] = o[j] > 0.f ? o[j] : expm1f(o[j]);
    ((float4*)g_emb)[idx] = make_float4(o[0], o[1], o[2], o[3]);
}

// ---------------- 5. con_adj = emb @ emb.T (symmetric, conflict-free LDS) ----------------
__global__ __launch_bounds__(256) void syrk_kernel(float* __restrict__ out) {
    const int bi = blockIdx.y, bj = blockIdx.x;
    if (bj < bi) return;

    __shared__ __align__(16) float As[16][132];
    __shared__ __align__(16) float Bs[16][132];
    const int i0 = bi * 128;
    const int j0 = bj * 128;
    const int tid = threadIdx.x;
    const int tx = tid & 15, ty = tid >> 4;

    ull acc2[8][4];
#pragma unroll
    for (int i = 0; i < 8; i++)
#pragma unroll
        for (int j = 0; j < 4; j++) acc2[i][j] = 0ull;

    const float4* E4 = (const float4*)g_emb;

    for (int kk = 0; kk < IN_DIM; kk += 16) {
#pragma unroll
        for (int e = 0; e < 2; e++) {
            int f = tid + e * 256;
            int row = f >> 2, cq = f & 3;
            float4 va = E4[(size_t)(i0 + row) * 32 + (kk >> 2) + cq];
            As[cq * 4 + 0][row] = va.x;
            As[cq * 4 + 1][row] = va.y;
            As[cq * 4 + 2][row] = va.z;
            As[cq * 4 + 3][row] = va.w;
            float4 vb = E4[(size_t)(j0 + row) * 32 + (kk >> 2) + cq];
            Bs[cq * 4 + 0][row] = vb.x;
            Bs[cq * 4 + 1][row] = vb.y;
            Bs[cq * 4 + 2][row] = vb.z;
            Bs[cq * 4 + 3][row] = vb.w;
        }
        __syncthreads();

#pragma unroll 4
        for (int k = 0; k < 16; k++) {
            float4 a0 = *(const float4*)&As[k][ty * 4];
            float4 a1 = *(const float4*)&As[k][64 + ty * 4];
            ulonglong2 bl0 = *(const ulonglong2*)&Bs[k][tx * 4];
            ulonglong2 bl1 = *(const ulonglong2*)&Bs[k][64 + tx * 4];
            float av[8] = {a0.x, a0.y, a0.z, a0.w, a1.x, a1.y, a1.z, a1.w};
#pragma unroll
            for (int i = 0; i < 8; i++) {
                ull ap = pack2(av[i], av[i]);
                ffma2(acc2[i][0], ap, bl0.x);
                ffma2(acc2[i][1], ap, bl0.y);
                ffma2(acc2[i][2], ap, bl1.x);
                ffma2(acc2[i][3], ap, bl1.y);
            }
        }
        __syncthreads();
    }

    float acc[8][8];
#pragma unroll
    for (int i = 0; i < 8; i++)
#pragma unroll
        for (int j4 = 0; j4 < 4; j4++) {
            float2 v = unpack2(acc2[i][j4]);
            acc[i][j4 * 2] = v.x;
            acc[i][j4 * 2 + 1] = v.y;
        }

#pragma unroll
    for (int i = 0; i < 8; i++) {
        int ri = (i < 4) ? (ty * 4 + i) : (64 + ty * 4 + i - 4);
        float* orow = out + (size_t)(i0 + ri) * NROWS;
        *(float4*)&orow[j0 + tx * 4] = make_float4(acc[i][0], acc[i][1], acc[i][2], acc[i][3]);
        *(float4*)&orow[j0 + 64 + tx * 4] = make_float4(acc[i][4], acc[i][5], acc[i][6], acc[i][7]);
    }
    if (bi != bj) {
#pragma unroll
        for (int j = 0; j < 8; j++) {
            int rj = (j < 4) ? (tx * 4 + j) : (64 + tx * 4 + j - 4);
            float* orow = out + (size_t)(j0 + rj) * NROWS;
            *(float4*)&orow[i0 + ty * 4] = make_float4(acc[0][j], acc[1][j], acc[2][j], acc[3][j]);
            *(float4*)&orow[i0 + 64 + ty * 4] = make_float4(acc[4][j], acc[5][j], acc[6][j], acc[7][j]);
        }
    }
}

// ---------------- 6. encoder: gates = x @ enc_W_ih.T, LSTM fused ----------------
__global__ __launch_bounds__(256) void enc_fused(const float* __restrict__ x,
                                                 const float* __restrict__ W,
                                                 const float* __restrict__ b_ih,
                                                 const float* __restrict__ b_hh) {
    __shared__ float As[16][128];
    __shared__ float Ws[16][257];
    __shared__ float gsm[16][256];
    const int i0 = blockIdx.x * 16;
    const int tid = threadIdx.x;
    const int n = tid;

    for (int idx = tid; idx < 16 * 128; idx += 256)
        As[idx >> 7][idx & 127] = x[(size_t)(i0 + (idx >> 7)) * 128 + (idx & 127)];

    float acc[16];
#pragma unroll
    for (int r = 0; r < 16; r++) acc[r] = 0.f;

    for (int kt = 0; kt < 128; kt += 16) {
        __syncthreads();
        for (int f = tid; f < 16 * 256; f += 256) {
            int n2 = f >> 4, kk = f & 15;
            Ws[kk][n2] = W[(size_t)n2 * 128 + kt + kk];
        }
        __syncthreads();
#pragma unroll
        for (int kk = 0; kk < 16; kk++) {
            float b = Ws[kk][n];
#pragma unroll
            for (int r = 0; r < 16; r++) acc[r] += As[r][kt + kk] * b;
        }
    }
    __syncthreads();
#pragma unroll
    for (int r = 0; r < 16; r++) gsm[r][n] = acc[r];
    __syncthreads();

#pragma unroll
    for (int e = 0; e < 4; e++) {
        int idx = tid + e * 256;
        int row = idx >> 6, hh = idx & 63;
        float gi = gsm[row][hh] + b_ih[hh] + b_hh[hh];
        float gg = gsm[row][128 + hh] + b_ih[128 + hh] + b_hh[128 + hh];
        float go = gsm[row][192 + hh] + b_ih[192 + hh] + b_hh[192 + hh];
        float c = sigmoidf_(gi) * tanhf(gg);
        g_henc[(size_t)(i0 + row) * 64 + hh] = sigmoidf_(go) * tanhf(c);
    }
}

// ---------------- 7. decoder: gates = h_enc @ dec_W_ih.T, LSTM fused ----------------
__global__ __launch_bounds__(512) void dec_fused(const float* __restrict__ W,
                                                 const float* __restrict__ b_ih,
                                                 const float* __restrict__ b_hh,
                                                 float* __restrict__ out) {
    __shared__ union {
        struct { float As[16][64]; float Ws[16][513]; } in;
        float gsm[16][512];
    } sm;
    const int i0 = blockIdx.x * 16;
    const int tid = threadIdx.x;
    const int n = tid;

    for (int idx = tid; idx < 16 * 64; idx += 512)
        sm.in.As[idx >> 6][idx & 63] = g_henc[(size_t)(i0 + (idx >> 6)) * 64 + (idx & 63)];

    float acc[16];
#pragma unroll
    for (int r = 0; r < 16; r++) acc[r] = 0.f;

    for (int kt = 0; kt < 64; kt += 16) {
        __syncthreads();
        for (int f = tid; f < 16 * 512; f += 512) {
            int n2 = f >> 4, kk = f & 15;
            sm.in.Ws[kk][n2] = W[(size_t)n2 * 64 + kt + kk];
        }
        __syncthreads();
#pragma unroll
        for (int kk = 0; kk < 16; kk++) {
            float b = sm.in.Ws[kk][n];
#pragma unroll
            for (int r = 0; r < 16; r++) acc[r] += sm.in.As[r][kt + kk] * b;
        }
    }
    __syncthreads();
#pragma unroll
    for (int r = 0; r < 16; r++) sm.gsm[r][n] = acc[r];
    __syncthreads();

#pragma unroll
    for (int e = 0; e < 4; e++) {
        int idx = tid + e * 512;
        int row = idx >> 7, hh = idx & 127;
        float gi = sm.gsm[row][hh] + b_ih[hh] + b_hh[hh];
        float gg = sm.gsm[row][256 + hh] + b_ih[256 + hh] + b_hh[256 + hh];
        float go = sm.gsm[row][384 + hh] + b_ih[384 + hh] + b_hh[384 + hh];
        float c = sigmoidf_(gi) * tanhf(gg);
        out[(size_t)(i0 + row) * 128 + hh] = sigmoidf_(go) * tanhf(c);
    }
}

// ---------------- launch ----------------
extern "C" void kernel_launch(void* const* d_in, const int* in_sizes, int n_in,
                              void* d_out, int out_size) {
    const float* x = (const float*)d_in[0];
    const float* adj = (const float*)d_in[1];
    const float* fea_W = (const float*)d_in[2];
    const float* fea_b = (const float*)d_in[3];
    const float* gat_W = (const float*)d_in[4];
    const float* gat_a = (const float*)d_in[5];
    const float* enc_W_ih = (const float*)d_in[6];
    const float* enc_b_ih = (const float*)d_in[8];
    const float* enc_b_hh = (const float*)d_in[9];
    const float* dec_W_ih = (const float*)d_in[10];
    const float* dec_b_ih = (const float*)d_in[12];
    const float* dec_b_hh = (const float*)d_in[13];

    float* out = (float*)d_out;
    float* con_adj = out;
    float* att_adj = out + (size_t)NROWS * NROWS;

    struct_kernel<<<NROWS / 16, 256>>>(x, fea_W, fea_b);                    // 1
    wh_s1s2_kernel<<<NROWS / 16, 256>>>(gat_W, gat_a);                      // 2
    vec_kernel<<<NROWS / 256, 256>>>();                                     // 3
    attn_partial_kernel<<<dim3(NROWS / 64, NSPLIT), 128>>>(adj);            // 4  <- ncu slot
    combine_kernel<<<NROWS * 32 / 256, 256>>>();                            // 5
    syrk_kernel<<<dim3(64, 64), 256>>>(con_adj);                            // 6
    enc_fused<<<NROWS / 16, 256>>>(x, enc_W_ih, enc_b_ih, enc_b_hh);        // 7
    dec_fused<<<NROWS / 16, 512>>>(dec_W_ih, dec_b_ih, dec_b_hh, att_adj);  // 8
}

// round 8
// speedup vs baseline: 1.9227x; 1.0016x over previous
#include <cuda_runtime.h>
#include <cuda_bf16.h>
#include <cstdint>

#define NROWS 8192
#define IN_DIM 128
#define HID 64
#define NSPLIT 16
#define JSEG (NROWS / NSPLIT)

typedef unsigned long long ull;

// ---------------- scratch (static device globals; no allocation) ----------------
__device__ __align__(16) float g_struct[NROWS * HID];
__device__ __align__(16) float g_Wh[NROWS * IN_DIM];
__device__ __align__(16) float g_s1[NROWS];
__device__ __align__(16) float g_s2[NROWS];
__device__ __align__(16) float g_A[NROWS];
__device__ __align__(16) float g_B[NROWS];
__device__ __align__(16) float g_C[NROWS];
__device__ __align__(16) float g_D[NROWS];
__device__ unsigned g_s2max_bits = 0u;   // atomicMax idempotent -> replay-deterministic
__device__ __align__(16) float g_henc[NROWS * HID];
__device__ __align__(16) __nv_bfloat16 g_embh[NROWS * IN_DIM];  // emb hi (bf16)
__device__ __align__(16) __nv_bfloat16 g_embl[NROWS * IN_DIM];  // emb lo (bf16)
__device__ __align__(16) float g_pacc[NSPLIT * NROWS * IN_DIM];
__device__ __align__(16) float g_pden[NSPLIT * NROWS];

// ---------------- helpers ----------------
__device__ __forceinline__ float sigmoidf_(float x) { return 1.0f / (1.0f + __expf(-x)); }

__device__ __forceinline__ unsigned float_key(float f) {
    unsigned b = __float_as_uint(f);
    return (b & 0x80000000u) ? ~b : (b | 0x80000000u);
}
__device__ __forceinline__ float key_float(unsigned k) {
    unsigned b = (k & 0x80000000u) ? (k & 0x7fffffffu) : ~k;
    return __uint_as_float(b);
}

__device__ __forceinline__ ull pack2(float lo, float hi) {
    ull r;
    asm("mov.b64 %0, {%1, %2};" : "=l"(r) : "f"(lo), "f"(hi));
    return r;
}
__device__ __forceinline__ void ffma2(ull& d, ull a, ull b) {
    asm("fma.rn.f32x2 %0, %1, %2, %3;" : "=l"(d) : "l"(a), "l"(b), "l"(d));
}
__device__ __forceinline__ float2 unpack2(ull v) {
    float2 r;
    asm("mov.b64 {%0, %1}, %2;" : "=f"(r.x), "=f"(r.y) : "l"(v));
    return r;
}
__device__ __forceinline__ uint32_t smem_u32(const void* p) {
    uint32_t a;
    asm("{ .reg .u64 t; cvta.to.shared.u64 t, %1; cvt.u32.u64 %0, t; }" : "=r"(a) : "l"(p));
    return a;
}

// ---------------- 1. structure = relu(x @ fea_W + fea_b) ----------------
__global__ __launch_bounds__(256) void struct_kernel(const float* __restrict__ A,
                                                     const float* __restrict__ W,
                                                     const float* __restrict__ bias) {
    __shared__ float As[16][128];
    const int i0 = blockIdx.x * 16;
    const int tid = threadIdx.x;
    const int n = tid & 63, rg = tid >> 6;

    for (int idx = tid; idx < 16 * 128; idx += 256)
        As[idx >> 7][idx & 127] = A[(size_t)(i0 + (idx >> 7)) * 128 + (idx & 127)];
    __syncthreads();

    float acc[4] = {0.f, 0.f, 0.f, 0.f};
#pragma unroll 4
    for (int k = 0; k < 128; k++) {
        float b = W[(size_t)k * 64 + n];
#pragma unroll
        for (int r = 0; r < 4; r++) acc[r] += As[rg * 4 + r][k] * b;
    }
    float bv = bias[n];
#pragma unroll
    for (int r = 0; r < 4; r++)
        g_struct[(size_t)(i0 + rg * 4 + r) * 64 + n] = fmaxf(acc[r] + bv, 0.f);
}

// ---------------- 2. Wh = structure @ gat_W, fused s1/s2/max(s2) ----------------
__global__ __launch_bounds__(256) void wh_s1s2_kernel(const float* __restrict__ W,
                                                      const float* __restrict__ gat_a) {
    __shared__ float As[16][64];
    __shared__ float r1[8][8], r2[8][8];
    const int i0 = blockIdx.x * 16;
    const int tid = threadIdx.x;
    const int n = tid & 127, rg = tid >> 7;

    for (int idx = tid; idx < 16 * 64; idx += 256)
        As[idx >> 6][idx & 63] = g_struct[(size_t)(i0 + (idx >> 6)) * 64 + (idx & 63)];
    __syncthreads();

    float acc[8];
#pragma unroll
    for (int r = 0; r < 8; r++) acc[r] = 0.f;
#pragma unroll 4
    for (int k = 0; k < 64; k++) {
        float b = W[(size_t)k * 128 + n];
#pragma unroll
        for (int r = 0; r < 8; r++) acc[r] += As[rg * 8 + r][k] * b;
    }
#pragma unroll
    for (int r = 0; r < 8; r++)
        g_Wh[(size_t)(i0 + rg * 8 + r) * 128 + n] = acc[r];

    float a1v = gat_a[n], a2v = gat_a[128 + n];
    int warp = tid >> 5, lane = tid & 31;
#pragma unroll
    for (int r = 0; r < 8; r++) {
        float v1 = acc[r] * a1v, v2 = acc[r] * a2v;
#pragma unroll
        for (int off = 16; off; off >>= 1) {
            v1 += __shfl_xor_sync(0xffffffffu, v1, off);
            v2 += __shfl_xor_sync(0xffffffffu, v2, off);
        }
        if (lane == 0) { r1[warp][r] = v1; r2[warp][r] = v2; }
    }
    __syncthreads();
    if (tid < 16) {
        int rgg = tid >> 3, rr = tid & 7;
        float s1 = r1[rgg * 4 + 0][rr] + r1[rgg * 4 + 1][rr] + r1[rgg * 4 + 2][rr] + r1[rgg * 4 + 3][rr];
        float s2 = r2[rgg * 4 + 0][rr] + r2[rgg * 4 + 1][rr] + r2[rgg * 4 + 2][rr] + r2[rgg * 4 + 3][rr];
        g_s1[i0 + tid] = s1;
        g_s2[i0 + tid] = s2;
        float m = s2;
#pragma unroll
        for (int off = 8; off; off >>= 1) m = fmaxf(m, __shfl_xor_sync(0x0000ffffu, m, off));
        if (tid == 0) atomicMax(&g_s2max_bits, float_key(m));
    }
}

// ---------------- 3. precompute A,B,C,D ----------------
__global__ void vec_kernel() {
    int i = blockIdx.x * 256 + threadIdx.x;
    float s2max = key_float(g_s2max_bits);
    float t = g_s1[i] + s2max;
    float m = t > 0.f ? t : 0.2f * t;
    g_A[i] = expf(t - m);
    g_C[i] = expf(0.2f * t - m);
    float u = g_s2[i] - s2max;
    g_B[i] = expf(u);
    g_D[i] = expf(0.2f * u);
}

// ---------------- 4. attention partial: 64x128 tile, pre-duplicated p pairs ----------------
__global__ __launch_bounds__(128, 4) void attn_partial_kernel(const float* __restrict__ adj) {
    __shared__ __align__(16) ull p_s2[64 * 34];      // [r][k] duplicated (p,p), stride 34 ull
    __shared__ __align__(16) float wh_s[32 * 128];   // [k][c]
    __shared__ float s1_s[64], A_s[64], C_s[64];

    const int i0 = blockIdx.x * 64;
    const int jb = blockIdx.y * JSEG;
    const int tid = threadIdx.x;
    if (tid < 64) {
        s1_s[tid] = g_s1[i0 + tid];
        A_s[tid] = g_A[i0 + tid];
        C_s[tid] = g_C[i0 + tid];
    }

    const int tx = tid & 15;        // GEMM cols tx*4..+3, 64+tx*4..+3
    const int ry = tid >> 4;        // GEMM rows ry*8..+7
    const int c4 = (tid & 7) * 4;   // build cols
    const int rp = tid >> 3;        // build rows rp*4..+3

    ull acc[8][4];
#pragma unroll
    for (int a = 0; a < 8; a++)
#pragma unroll
        for (int b = 0; b < 4; b++) acc[a][b] = 0ull;
    float dsum[4] = {0.f, 0.f, 0.f, 0.f};

    const float4* Wh4 = (const float4*)g_Wh;
    const float4* S24 = (const float4*)g_s2;
    const float4* B4 = (const float4*)g_B;
    const float4* D4 = (const float4*)g_D;

    for (int jc = jb; jc < jb + JSEG; jc += 32) {
        __syncthreads();

#pragma unroll
        for (int e = 0; e < 8; e++) {
            int idx = tid + e * 128;
            int k = idx >> 5, q = idx & 31;
            ((float4*)wh_s)[k * 32 + q] = Wh4[(size_t)(jc + k) * 32 + q];
        }

        {
            float4 s2v = S24[(jc >> 2) + (tid & 7)];
            float4 Bv = B4[(jc >> 2) + (tid & 7)];
            float4 Dv = D4[(jc >> 2) + (tid & 7)];
#pragma unroll
            for (int rr = 0; rr < 4; rr++) {
                int r = rp * 4 + rr;
                float4 av = *(const float4*)&adj[(size_t)(i0 + r) * NROWS + jc + c4];
                float s1 = s1_s[r], Av = A_s[r], Cv = C_s[r];
                float4 pv;
                { float t = s1 + s2v.x; pv.x = (av.x > 0.f) ? (t > 0.f ? Av * Bv.x : Cv * Dv.x) : 0.f; }
                { float t = s1 + s2v.y; pv.y = (av.y > 0.f) ? (t > 0.f ? Av * Bv.y : Cv * Dv.y) : 0.f; }
                { float t = s1 + s2v.z; pv.z = (av.z > 0.f) ? (t > 0.f ? Av * Bv.z : Cv * Dv.z) : 0.f; }
                { float t = s1 + s2v.w; pv.w = (av.w > 0.f) ? (t > 0.f ? Av * Bv.w : Cv * Dv.w) : 0.f; }
                *(ulonglong2*)&p_s2[r * 34 + c4] = make_ulonglong2(pack2(pv.x, pv.x), pack2(pv.y, pv.y));
                *(ulonglong2*)&p_s2[r * 34 + c4 + 2] = make_ulonglong2(pack2(pv.z, pv.z), pack2(pv.w, pv.w));
                dsum[rr] += (pv.x + pv.y) + (pv.z + pv.w);
            }
        }
        __syncthreads();

        // acc += p(64x32) @ wh(32x128); pre-packed p pairs: zero pack instructions
#pragma unroll 4
        for (int k = 0; k < 32; k += 2) {
            ulonglong2 b0a = *(const ulonglong2*)&wh_s[k * 128 + tx * 4];
            ulonglong2 b1a = *(const ulonglong2*)&wh_s[k * 128 + 64 + tx * 4];
            ulonglong2 b0b = *(const ulonglong2*)&wh_s[(k + 1) * 128 + tx * 4];
            ulonglong2 b1b = *(const ulonglong2*)&wh_s[(k + 1) * 128 + 64 + tx * 4];
#pragma unroll
            for (int r = 0; r < 8; r++) {
                ulonglong2 pp = *(const ulonglong2*)&p_s2[(ry * 8 + r) * 34 + k];
                ffma2(acc[r][0], pp.x, b0a.x);
                ffma2(acc[r][1], pp.x, b0a.y);
                ffma2(acc[r][2], pp.x, b1a.x);
                ffma2(acc[r][3], pp.x, b1a.y);
                ffma2(acc[r][0], pp.y, b0b.x);
                ffma2(acc[r][1], pp.y, b0b.y);
                ffma2(acc[r][2], pp.y, b1b.x);
                ffma2(acc[r][3], pp.y, b1b.y);
            }
        }
    }

#pragma unroll
    for (int off = 4; off; off >>= 1) {
#pragma unroll
        for (int rr = 0; rr < 4; rr++)
            dsum[rr] += __shfl_down_sync(0xffffffffu, dsum[rr], off, 8);
    }
    if ((tid & 7) == 0) {
#pragma unroll
        for (int rr = 0; rr < 4; rr++)
            g_pden[(size_t)blockIdx.y * NROWS + i0 + rp * 4 + rr] = dsum[rr];
    }

    float* pa = g_pacc + (size_t)blockIdx.y * NROWS * IN_DIM;
#pragma unroll
    for (int r = 0; r < 8; r++) {
        int row = i0 + ry * 8 + r;
        float2 v0 = unpack2(acc[r][0]), v1 = unpack2(acc[r][1]);
        float2 v2 = unpack2(acc[r][2]), v3 = unpack2(acc[r][3]);
        *(float4*)&pa[(size_t)row * IN_DIM + tx * 4] = make_float4(v0.x, v0.y, v1.x, v1.y);
        *(float4*)&pa[(size_t)row * IN_DIM + 64 + tx * 4] = make_float4(v2.x, v2.y, v3.x, v3.y);
    }
}

// ---------------- 4b. combine: emb = elu(sum/den), split to bf16 hi+lo ----------------
__global__ __launch_bounds__(256) void combine_kernel() {
    int idx = blockIdx.x * 256 + threadIdx.x;        // float4 granularity
    int row = idx >> 5;
    float den = 0.f;
    float4 acc = make_float4(0.f, 0.f, 0.f, 0.f);
#pragma unroll
    for (int s = 0; s < NSPLIT; s++) {
        den += g_pden[(size_t)s * NROWS + row];
        float4 v = ((const float4*)g_pacc)[(size_t)s * NROWS * 32 + idx];
        acc.x += v.x; acc.y += v.y; acc.z += v.z; acc.w += v.w;
    }
    float inv = 1.0f / den;
    float o[4] = {acc.x * inv, acc.y * inv, acc.z * inv, acc.w * inv};
    __nv_bfloat16 hi[4], lo[4];
#pragma unroll
    for (int j = 0; j < 4; j++) {
        o[j] = o[j] > 0.f ? o[j] : expm1f(o[j]);
        hi[j] = __float2bfloat16(o[j]);
        lo[j] = __float2bfloat16(o[j] - __bfloat162float(hi[j]));
    }
    *(ull*)&g_embh[(size_t)idx * 4] = *(const ull*)hi;
    *(ull*)&g_embl[(size_t)idx * 4] = *(const ull*)lo;
}

// ---------------- 5. con_adj = emb @ emb.T via mma.sync bf16 split (HMMA fallback) ----------------
#define LDB 136                      // padded bf16 row stride: 272B = 17*16B, conflict-free ldmatrix
#define TILE_ELEMS (128 * LDB)
#define SYRK_SMEM (4 * TILE_ELEMS * 2)

__device__ __forceinline__ void ldm_x4(uint32_t* a, uint32_t addr) {
    asm volatile("ldmatrix.sync.aligned.m8n8.x4.shared.b16 {%0,%1,%2,%3}, [%4];"
                 : "=r"(a[0]), "=r"(a[1]), "=r"(a[2]), "=r"(a[3]) : "r"(addr));
}
__device__ __forceinline__ void ldm_x2(uint32_t* b, uint32_t addr) {
    asm volatile("ldmatrix.sync.aligned.m8n8.x2.shared.b16 {%0,%1}, [%2];"
                 : "=r"(b[0]), "=r"(b[1]) : "r"(addr));
}
__device__ __forceinline__ void mma16816(float* d, const uint32_t* a, const uint32_t* b) {
    asm volatile("mma.sync.aligned.m16n8k16.row.col.f32.bf16.bf16.f32 "
                 "{%0,%1,%2,%3}, {%4,%5,%6,%7}, {%8,%9}, {%0,%1,%2,%3};"
                 : "+f"(d[0]), "+f"(d[1]), "+f"(d[2]), "+f"(d[3])
                 : "r"(a[0]), "r"(a[1]), "r"(a[2]), "r"(a[3]), "r"(b[0]), "r"(b[1]));
}

// one 3-pass split-bf16 accumulation: d += (Ah+Al)(Bh+Bl)^T (dropping lo*lo)
__device__ __forceinline__ void syrk_mma_phase(
    const __nv_bfloat16* Ah, const __nv_bfloat16* Al,
    const __nv_bfloat16* Bh, const __nv_bfloat16* Bl,
    int m0, int n0, int lane, float d[4][4][4]) {
#pragma unroll
    for (int pass = 0; pass < 3; pass++) {
        const __nv_bfloat16* Ap = (pass == 2) ? Al : Ah;
        const __nv_bfloat16* Bp = (pass == 1) ? Bl : Bh;
        uint32_t a_base = smem_u32(Ap);
        uint32_t b_base = smem_u32(Bp);
#pragma unroll
        for (int ks = 0; ks < 8; ks++) {
            int k0 = ks * 16;
            uint32_t afr[4][4], bfr[4][2];
#pragma unroll
            for (int mt = 0; mt < 4; mt++) {
                int row = m0 + mt * 16 + (lane & 15);
                int col = k0 + (lane >> 4) * 8;
                ldm_x4(afr[mt], a_base + (row * LDB + col) * 2);
            }
#pragma unroll
            for (int nt = 0; nt < 4; nt++) {
                int row = n0 + nt * 8 + (lane & 7);
                int col = k0 + ((lane >> 3) & 1) * 8;
                ldm_x2(bfr[nt], b_base + (row * LDB + col) * 2);
            }
#pragma unroll
            for (int mt = 0; mt < 4; mt++)
#pragma unroll
                for (int nt = 0; nt < 4; nt++)
                    mma16816(d[mt][nt], afr[mt], bfr[nt]);
        }
    }
}

__global__ __launch_bounds__(256) void syrk_mma_kernel(float* __restrict__ out) {
    const int bi = blockIdx.y, bj = blockIdx.x;
    if (bj < bi) return;
    extern __shared__ __nv_bfloat16 sm[];
    __nv_bfloat16* Ah = sm;
    __nv_bfloat16* Al = Ah + TILE_ELEMS;
    __nv_bfloat16* Bh = Al + TILE_ELEMS;
    __nv_bfloat16* Bl = Bh + TILE_ELEMS;

    const int tid = threadIdx.x;
    const int lane = tid & 31, wid = tid >> 5;
    const int i0 = bi * 128, j0 = bj * 128;
    const int m0 = (wid & 1) * 64, n0 = (wid >> 1) * 32;   // warp tile 64x32
    const int g = lane >> 2, tig = lane & 3;

    // load 4 tiles: 128 rows x 128 bf16 each (uint4 = 8 bf16, 16 per row)
    const uint4* EH = (const uint4*)g_embh;
    const uint4* EL = (const uint4*)g_embl;
#pragma unroll
    for (int e = 0; e < 8; e++) {
        int idx = tid + e * 256;
        int row = idx >> 4, ch = idx & 15;
        *(uint4*)&Ah[row * LDB + ch * 8] = EH[(size_t)(i0 + row) * 16 + ch];
        *(uint4*)&Al[row * LDB + ch * 8] = EL[(size_t)(i0 + row) * 16 + ch];
        *(uint4*)&Bh[row * LDB + ch * 8] = EH[(size_t)(j0 + row) * 16 + ch];
        *(uint4*)&Bl[row * LDB + ch * 8] = EL[(size_t)(j0 + row) * 16 + ch];
    }
    __syncthreads();

    float d[4][4][4];
#pragma unroll
    for (int mt = 0; mt < 4; mt++)
#pragma unroll
        for (int nt = 0; nt < 4; nt++)
#pragma unroll
            for (int q = 0; q < 4; q++) d[mt][nt][q] = 0.f;

    syrk_mma_phase(Ah, Al, Bh, Bl, m0, n0, lane, d);

#pragma unroll
    for (int mt = 0; mt < 4; mt++) {
        int r0 = i0 + m0 + mt * 16 + g;
#pragma unroll
        for (int nt = 0; nt < 4; nt++) {
            int c0 = j0 + n0 + nt * 8 + tig * 2;
            *(float2*)&out[(size_t)r0 * NROWS + c0] = make_float2(d[mt][nt][0], d[mt][nt][1]);
            *(float2*)&out[(size_t)(r0 + 8) * NROWS + c0] = make_float2(d[mt][nt][2], d[mt][nt][3]);
        }
    }

    if (bi != bj) {
        // mirror tile: D' = B * A^T, same smem, roles swapped
#pragma unroll
        for (int mt = 0; mt < 4; mt++)
#pragma unroll
            for (int nt = 0; nt < 4; nt++)
#pragma unroll
                for (int q = 0; q < 4; q++) d[mt][nt][q] = 0.f;

        syrk_mma_phase(Bh, Bl, Ah, Al, m0, n0, lane, d);

#pragma unroll
        for (int mt = 0; mt < 4; mt++) {
            int r0 = j0 + m0 + mt * 16 + g;
#pragma unroll
            for (int nt = 0; nt < 4; nt++) {
                int c0 = i0 + n0 + nt * 8 + tig * 2;
                *(float2*)&out[(size_t)r0 * NROWS + c0] = make_float2(d[mt][nt][0], d[mt][nt][1]);
                *(float2*)&out[(size_t)(r0 + 8) * NROWS + c0] = make_float2(d[mt][nt][2], d[mt][nt][3]);
            }
        }
    }
}

// ---------------- 6. encoder: gates = x @ enc_W_ih.T, LSTM fused ----------------
__global__ __launch_bounds__(256) void enc_fused(const float* __restrict__ x,
                                                 const float* __restrict__ W,
                                                 const float* __restrict__ b_ih,
                                                 const float* __restrict__ b_hh) {
    __shared__ float As[16][128];
    __shared__ float Ws[16][257];
    __shared__ float gsm[16][256];
    const int i0 = blockIdx.x * 16;
    const int tid = threadIdx.x;
    const int n = tid;

    for (int idx = tid; idx < 16 * 128; idx += 256)
        As[idx >> 7][idx & 127] = x[(size_t)(i0 + (idx >> 7)) * 128 + (idx & 127)];

    float acc[16];
#pragma unroll
    for (int r = 0; r < 16; r++) acc[r] = 0.f;

    for (int kt = 0; kt < 128; kt += 16) {
        __syncthreads();
        for (int f = tid; f < 16 * 256; f += 256) {
            int n2 = f >> 4, kk = f & 15;
            Ws[kk][n2] = W[(size_t)n2 * 128 + kt + kk];
        }
        __syncthreads();
#pragma unroll
        for (int kk = 0; kk < 16; kk++) {
            float b = Ws[kk][n];
#pragma unroll
            for (int r = 0; r < 16; r++) acc[r] += As[r][kt + kk] * b;
        }
    }
    __syncthreads();
#pragma unroll
    for (int r = 0; r < 16; r++) gsm[r][n] = acc[r];
    __syncthreads();

#pragma unroll
    for (int e = 0; e < 4; e++) {
        int idx = tid + e * 256;
        int row = idx >> 6, hh = idx & 63;
        float gi = gsm[row][hh] + b_ih[hh] + b_hh[hh];
        float gg = gsm[row][128 + hh] + b_ih[128 + hh] + b_hh[128 + hh];
        float go = gsm[row][192 + hh] + b_ih[192 + hh] + b_hh[192 + hh];
        float c = sigmoidf_(gi) * tanhf(gg);
        g_henc[(size_t)(i0 + row) * 64 + hh] = sigmoidf_(go) * tanhf(c);
    }
}

// ---------------- 7. decoder: gates = h_enc @ dec_W_ih.T, LSTM fused ----------------
__global__ __launch_bounds__(512) void dec_fused(const float* __restrict__ W,
                                                 const float* __restrict__ b_ih,
                                                 const float* __restrict__ b_hh,
                                                 float* __restrict__ out) {
    __shared__ union {
        struct { float As[16][64]; float Ws[16][513]; } in;
        float gsm[16][512];
    } sm;
    const int i0 = blockIdx.x * 16;
    const int tid = threadIdx.x;
    const int n = tid;

    for (int idx = tid; idx < 16 * 64; idx += 512)
        sm.in.As[idx >> 6][idx & 63] = g_henc[(size_t)(i0 + (idx >> 6)) * 64 + (idx & 63)];

    float acc[16];
#pragma unroll
    for (int r = 0; r < 16; r++) acc[r] = 0.f;

    for (int kt = 0; kt < 64; kt += 16) {
        __syncthreads();
        for (int f = tid; f < 16 * 512; f += 512) {
            int n2 = f >> 4, kk = f & 15;
            sm.in.Ws[kk][n2] = W[(size_t)n2 * 64 + kt + kk];
        }
        __syncthreads();
#pragma unroll
        for (int kk = 0; kk < 16; kk++) {
            float b = sm.in.Ws[kk][n];
#pragma unroll
            for (int r = 0; r < 16; r++) acc[r] += sm.in.As[r][kt + kk] * b;
        }
    }
    __syncthreads();
#pragma unroll
    for (int r = 0; r < 16; r++) sm.gsm[r][n] = acc[r];
    __syncthreads();

#pragma unroll
    for (int e = 0; e < 4; e++) {
        int idx = tid + e * 512;
        int row = idx >> 7, hh = idx & 127;
        float gi = sm.gsm[row][hh] + b_ih[hh] + b_hh[hh];
        float gg = sm.gsm[row][256 + hh] + b_ih[256 + hh] + b_hh[256 + hh];
        float go = sm.gsm[row][384 + hh] + b_ih[384 + hh] + b_hh[384 + hh];
        float c = sigmoidf_(gi) * tanhf(gg);
        out[(size_t)(i0 + row) * 128 + hh] = sigmoidf_(go) * tanhf(c);
    }
}

// ---------------- launch ----------------
extern "C" void kernel_launch(void* const* d_in, const int* in_sizes, int n_in,
                              void* d_out, int out_size) {
    const float* x = (const float*)d_in[0];
    const float* adj = (const float*)d_in[1];
    const float* fea_W = (const float*)d_in[2];
    const float* fea_b = (const float*)d_in[3];
    const float* gat_W = (const float*)d_in[4];
    const float* gat_a = (const float*)d_in[5];
    const float* enc_W_ih = (const float*)d_in[6];
    const float* enc_b_ih = (const float*)d_in[8];
    const float* enc_b_hh = (const float*)d_in[9];
    const float* dec_W_ih = (const float*)d_in[10];
    const float* dec_b_ih = (const float*)d_in[12];
    const float* dec_b_hh = (const float*)d_in[13];

    float* out = (float*)d_out;
    float* con_adj = out;
    float* att_adj = out + (size_t)NROWS * NROWS;

    cudaFuncSetAttribute(syrk_mma_kernel, cudaFuncAttributeMaxDynamicSharedMemorySize, SYRK_SMEM);

    struct_kernel<<<NROWS / 16, 256>>>(x, fea_W, fea_b);                    // 1
    wh_s1s2_kernel<<<NROWS / 16, 256>>>(gat_W, gat_a);                      // 2
    vec_kernel<<<NROWS / 256, 256>>>();                                     // 3
    attn_partial_kernel<<<dim3(NROWS / 64, NSPLIT), 128>>>(adj);            // 4  <- ncu slot
    combine_kernel<<<NROWS * 32 / 256, 256>>>();                            // 5
    syrk_mma_kernel<<<dim3(64, 64), 256, SYRK_SMEM>>>(con_adj);             // 6
    enc_fused<<<NROWS / 16, 256>>>(x, enc_W_ih, enc_b_ih, enc_b_hh);        // 7
    dec_fused<<<NROWS / 16, 512>>>(dec_W_ih, dec_b_ih, dec_b_hh, att_adj);  // 8
}

// round 9
// speedup vs baseline: 2.7612x; 1.4361x over previous
#include <cuda_runtime.h>
#include <cuda_bf16.h>
#include <cstdint>

#define NROWS 8192
#define IN_DIM 128
#define HID 64
#define NSPLIT 16
#define JSEG (NROWS / NSPLIT)

typedef unsigned long long ull;

// ---------------- scratch (static device globals; no allocation) ----------------
__device__ __align__(16) float g_struct[NROWS * HID];
__device__ __align__(16) __nv_bfloat16 g_Whh[NROWS * IN_DIM];   // Wh hi (bf16)
__device__ __align__(16) __nv_bfloat16 g_Whl[NROWS * IN_DIM];   // Wh lo (bf16)
__device__ __align__(16) float g_s1[NROWS];
__device__ __align__(16) float g_s2[NROWS];
__device__ __align__(16) float g_A[NROWS];
__device__ __align__(16) float g_B[NROWS];
__device__ __align__(16) float g_C[NROWS];
__device__ __align__(16) float g_D[NROWS];
__device__ unsigned g_s2max_bits = 0u;   // atomicMax idempotent -> replay-deterministic
__device__ __align__(16) float g_henc[NROWS * HID];
__device__ __align__(16) __nv_bfloat16 g_embh[NROWS * IN_DIM];
__device__ __align__(16) __nv_bfloat16 g_embl[NROWS * IN_DIM];
__device__ __align__(16) float g_pacc[NSPLIT * NROWS * IN_DIM];
__device__ __align__(16) float g_pden[NSPLIT * NROWS];

// ---------------- helpers ----------------
__device__ __forceinline__ float sigmoidf_(float x) { return 1.0f / (1.0f + __expf(-x)); }

__device__ __forceinline__ unsigned float_key(float f) {
    unsigned b = __float_as_uint(f);
    return (b & 0x80000000u) ? ~b : (b | 0x80000000u);
}
__device__ __forceinline__ float key_float(unsigned k) {
    unsigned b = (k & 0x80000000u) ? (k & 0x7fffffffu) : ~k;
    return __uint_as_float(b);
}
__device__ __forceinline__ uint32_t smem_u32(const void* p) {
    uint32_t a;
    asm("{ .reg .u64 t; cvta.to.shared.u64 t, %1; cvt.u32.u64 %0, t; }" : "=r"(a) : "l"(p));
    return a;
}

// ---------------- mma.sync helpers (bf16, m16n8k16) ----------------
__device__ __forceinline__ void ldm_x4(uint32_t* a, uint32_t addr) {
    asm volatile("ldmatrix.sync.aligned.m8n8.x4.shared.b16 {%0,%1,%2,%3}, [%4];"
                 : "=r"(a[0]), "=r"(a[1]), "=r"(a[2]), "=r"(a[3]) : "r"(addr));
}
__device__ __forceinline__ void ldm_x4t(uint32_t* a, uint32_t addr) {
    asm volatile("ldmatrix.sync.aligned.m8n8.x4.trans.shared.b16 {%0,%1,%2,%3}, [%4];"
                 : "=r"(a[0]), "=r"(a[1]), "=r"(a[2]), "=r"(a[3]) : "r"(addr));
}
__device__ __forceinline__ void ldm_x2(uint32_t* b, uint32_t addr) {
    asm volatile("ldmatrix.sync.aligned.m8n8.x2.shared.b16 {%0,%1}, [%2];"
                 : "=r"(b[0]), "=r"(b[1]) : "r"(addr));
}
__device__ __forceinline__ void mma16816(float* d, const uint32_t* a, const uint32_t* b) {
    asm volatile("mma.sync.aligned.m16n8k16.row.col.f32.bf16.bf16.f32 "
                 "{%0,%1,%2,%3}, {%4,%5,%6,%7}, {%8,%9}, {%0,%1,%2,%3};"
                 : "+f"(d[0]), "+f"(d[1]), "+f"(d[2]), "+f"(d[3])
                 : "r"(a[0]), "r"(a[1]), "r"(a[2]), "r"(a[3]), "r"(b[0]), "r"(b[1]));
}

// ---------------- 1. structure = relu(x @ fea_W + fea_b) ----------------
__global__ __launch_bounds__(256) void struct_kernel(const float* __restrict__ A,
                                                     const float* __restrict__ W,
                                                     const float* __restrict__ bias) {
    __shared__ float As[16][128];
    const int i0 = blockIdx.x * 16;
    const int tid = threadIdx.x;
    const int n = tid & 63, rg = tid >> 6;

    for (int idx = tid; idx < 16 * 128; idx += 256)
        As[idx >> 7][idx & 127] = A[(size_t)(i0 + (idx >> 7)) * 128 + (idx & 127)];
    __syncthreads();

    float acc[4] = {0.f, 0.f, 0.f, 0.f};
#pragma unroll 4
    for (int k = 0; k < 128; k++) {
        float b = W[(size_t)k * 64 + n];
#pragma unroll
        for (int r = 0; r < 4; r++) acc[r] += As[rg * 4 + r][k] * b;
    }
    float bv = bias[n];
#pragma unroll
    for (int r = 0; r < 4; r++)
        g_struct[(size_t)(i0 + rg * 4 + r) * 64 + n] = fmaxf(acc[r] + bv, 0.f);
}

// ---------------- 2. Wh = structure @ gat_W (bf16 hi/lo), fused s1/s2/max(s2) ----------------
__global__ __launch_bounds__(256) void wh_s1s2_kernel(const float* __restrict__ W,
                                                      const float* __restrict__ gat_a) {
    __shared__ float As[16][64];
    __shared__ float r1[8][8], r2[8][8];
    const int i0 = blockIdx.x * 16;
    const int tid = threadIdx.x;
    const int n = tid & 127, rg = tid >> 7;

    for (int idx = tid; idx < 16 * 64; idx += 256)
        As[idx >> 6][idx & 63] = g_struct[(size_t)(i0 + (idx >> 6)) * 64 + (idx & 63)];
    __syncthreads();

    float acc[8];
#pragma unroll
    for (int r = 0; r < 8; r++) acc[r] = 0.f;
#pragma unroll 4
    for (int k = 0; k < 64; k++) {
        float b = W[(size_t)k * 128 + n];
#pragma unroll
        for (int r = 0; r < 8; r++) acc[r] += As[rg * 8 + r][k] * b;
    }
#pragma unroll
    for (int r = 0; r < 8; r++) {
        float v = acc[r];
        __nv_bfloat16 hi = __float2bfloat16(v);
        __nv_bfloat16 lo = __float2bfloat16(v - __bfloat162float(hi));
        g_Whh[(size_t)(i0 + rg * 8 + r) * 128 + n] = hi;
        g_Whl[(size_t)(i0 + rg * 8 + r) * 128 + n] = lo;
    }

    float a1v = gat_a[n], a2v = gat_a[128 + n];
    int warp = tid >> 5, lane = tid & 31;
#pragma unroll
    for (int r = 0; r < 8; r++) {
        float v1 = acc[r] * a1v, v2 = acc[r] * a2v;
#pragma unroll
        for (int off = 16; off; off >>= 1) {
            v1 += __shfl_xor_sync(0xffffffffu, v1, off);
            v2 += __shfl_xor_sync(0xffffffffu, v2, off);
        }
        if (lane == 0) { r1[warp][r] = v1; r2[warp][r] = v2; }
    }
    __syncthreads();
    if (tid < 16) {
        int rgg = tid >> 3, rr = tid & 7;
        float s1 = r1[rgg * 4 + 0][rr] + r1[rgg * 4 + 1][rr] + r1[rgg * 4 + 2][rr] + r1[rgg * 4 + 3][rr];
        float s2 = r2[rgg * 4 + 0][rr] + r2[rgg * 4 + 1][rr] + r2[rgg * 4 + 2][rr] + r2[rgg * 4 + 3][rr];
        g_s1[i0 + tid] = s1;
        g_s2[i0 + tid] = s2;
        float m = s2;
#pragma unroll
        for (int off = 8; off; off >>= 1) m = fmaxf(m, __shfl_xor_sync(0x0000ffffu, m, off));
        if (tid == 0) atomicMax(&g_s2max_bits, float_key(m));
    }
}

// ---------------- 3. precompute A,B,C,D ----------------
__global__ void vec_kernel() {
    int i = blockIdx.x * 256 + threadIdx.x;
    float s2max = key_float(g_s2max_bits);
    float t = g_s1[i] + s2max;
    float m = t > 0.f ? t : 0.2f * t;
    g_A[i] = expf(t - m);
    g_C[i] = expf(0.2f * t - m);
    float u = g_s2[i] - s2max;
    g_B[i] = expf(u);
    g_D[i] = expf(0.2f * u);
}

// ---------------- 4. attention partial via mma.sync split-bf16 ----------------
// Block tile 64(i) x 128(c); j-chunk 32; 8 warps (2x4), warp tile 32x32.
// p built fp32 (exact denominators), split hi/lo bf16; 3 MMA passes: ph*Whh + pl*Whh + ph*Whl.
#define PLD 40     // p smem stride (bf16)
#define WLD 136    // Wh smem stride (bf16)
__global__ __launch_bounds__(256) void attn_mma_kernel(const float* __restrict__ adj) {
    __shared__ __align__(16) __nv_bfloat16 ph_s[64 * PLD];
    __shared__ __align__(16) __nv_bfloat16 pl_s[64 * PLD];
    __shared__ __align__(16) __nv_bfloat16 whh_s[32 * WLD];
    __shared__ __align__(16) __nv_bfloat16 whl_s[32 * WLD];
    __shared__ float s1_s[64], A_s[64], C_s[64];

    const int i0 = blockIdx.x * 64;
    const int jb = blockIdx.y * JSEG;
    const int tid = threadIdx.x;
    const int lane = tid & 31, wid = tid >> 5;
    const int wm = wid & 1, wn = wid >> 1;          // warp grid 2(M) x 4(N)
    if (tid < 64) {
        s1_s[tid] = g_s1[i0 + tid];
        A_s[tid] = g_A[i0 + tid];
        C_s[tid] = g_C[i0 + tid];
    }

    const int c4 = (tid & 7) * 4;    // build cols
    const int rp = tid >> 3;         // build rows rp*2, rp*2+1

    float d[2][4][4];
#pragma unroll
    for (int mt = 0; mt < 2; mt++)
#pragma unroll
        for (int nt = 0; nt < 4; nt++)
#pragma unroll
            for (int q = 0; q < 4; q++) d[mt][nt][q] = 0.f;
    float dsum[2] = {0.f, 0.f};

    const uint4* WHH4 = (const uint4*)g_Whh;
    const uint4* WHL4 = (const uint4*)g_Whl;
    const float4* S24 = (const float4*)g_s2;
    const float4* B4 = (const float4*)g_B;
    const float4* D4 = (const float4*)g_D;

    const uint32_t ph_b = smem_u32(ph_s), pl_b = smem_u32(pl_s);
    const uint32_t whh_b = smem_u32(whh_s), whl_b = smem_u32(whl_s);

    for (int jc = jb; jc < jb + JSEG; jc += 32) {
        __syncthreads();

        // Wh hi/lo tiles: 32 k-rows x 128 cols (16 uint4 per row)
#pragma unroll
        for (int e = 0; e < 2; e++) {
            int idx = tid + e * 256;
            int row = idx >> 4, ch = idx & 15;
            *(uint4*)&whh_s[row * WLD + ch * 8] = WHH4[(size_t)(jc + row) * 16 + ch];
            *(uint4*)&whl_s[row * WLD + ch * 8] = WHL4[(size_t)(jc + row) * 16 + ch];
        }

        // p tile 64x32 fp32 -> bf16 hi/lo
        {
            float4 s2v = S24[(jc >> 2) + (tid & 7)];
            float4 Bv = B4[(jc >> 2) + (tid & 7)];
            float4 Dv = D4[(jc >> 2) + (tid & 7)];
#pragma unroll
            for (int rr = 0; rr < 2; rr++) {
                int r = rp * 2 + rr;
                float4 av = *(const float4*)&adj[(size_t)(i0 + r) * NROWS + jc + c4];
                float s1 = s1_s[r], Av = A_s[r], Cv = C_s[r];
                float pv[4];
                { float t = s1 + s2v.x; pv[0] = (av.x > 0.f) ? (t > 0.f ? Av * Bv.x : Cv * Dv.x) : 0.f; }
                { float t = s1 + s2v.y; pv[1] = (av.y > 0.f) ? (t > 0.f ? Av * Bv.y : Cv * Dv.y) : 0.f; }
                { float t = s1 + s2v.z; pv[2] = (av.z > 0.f) ? (t > 0.f ? Av * Bv.z : Cv * Dv.z) : 0.f; }
                { float t = s1 + s2v.w; pv[3] = (av.w > 0.f) ? (t > 0.f ? Av * Bv.w : Cv * Dv.w) : 0.f; }
                ushort4 h4, l4;
                unsigned short* hp = (unsigned short*)&h4;
                unsigned short* lp = (unsigned short*)&l4;
#pragma unroll
                for (int q = 0; q < 4; q++) {
                    __nv_bfloat16 hi = __float2bfloat16(pv[q]);
                    __nv_bfloat16 lo = __float2bfloat16(pv[q] - __bfloat162float(hi));
                    hp[q] = *(unsigned short*)&hi;
                    lp[q] = *(unsigned short*)&lo;
                }
                *(ushort4*)&ph_s[r * PLD + c4] = h4;
                *(ushort4*)&pl_s[r * PLD + c4] = l4;
                dsum[rr] += (pv[0] + pv[1]) + (pv[2] + pv[3]);
            }
        }
        __syncthreads();

        // MMA: d += ph*Whh + pl*Whh + ph*Whl
#pragma unroll
        for (int ks = 0; ks < 2; ks++) {
            int k0 = ks * 16;
            uint32_t aph[2][4], apl[2][4], bhh[2][4], bhl[2][4];
#pragma unroll
            for (int mt = 0; mt < 2; mt++) {
                uint32_t off = ((wm * 32 + mt * 16 + (lane & 15)) * PLD + k0 + (lane >> 4) * 8) * 2;
                ldm_x4(aph[mt], ph_b + off);
                ldm_x4(apl[mt], pl_b + off);
            }
#pragma unroll
            for (int np = 0; np < 2; np++) {
                uint32_t off = ((k0 + (lane & 15)) * WLD + wn * 32 + np * 16 + (lane >> 4) * 8) * 2;
                ldm_x4t(bhh[np], whh_b + off);
                ldm_x4t(bhl[np], whl_b + off);
            }
#pragma unroll
            for (int mt = 0; mt < 2; mt++)
#pragma unroll
                for (int np = 0; np < 2; np++)
#pragma unroll
                    for (int h = 0; h < 2; h++) {
                        int nt = np * 2 + h;
                        mma16816(d[mt][nt], aph[mt], &bhh[np][h * 2]);
                        mma16816(d[mt][nt], apl[mt], &bhh[np][h * 2]);
                        mma16816(d[mt][nt], aph[mt], &bhl[np][h * 2]);
                    }
        }
    }

    // partial denominators (8 lanes per row pair)
#pragma unroll
    for (int off = 4; off; off >>= 1) {
        dsum[0] += __shfl_down_sync(0xffffffffu, dsum[0], off, 8);
        dsum[1] += __shfl_down_sync(0xffffffffu, dsum[1], off, 8);
    }
    if ((tid & 7) == 0) {
        g_pden[(size_t)blockIdx.y * NROWS + i0 + rp * 2] = dsum[0];
        g_pden[(size_t)blockIdx.y * NROWS + i0 + rp * 2 + 1] = dsum[1];
    }

    // partial accumulators
    float* pa = g_pacc + (size_t)blockIdx.y * NROWS * IN_DIM;
    const int g = lane >> 2, tig = lane & 3;
#pragma unroll
    for (int mt = 0; mt < 2; mt++) {
        int r0 = i0 + wm * 32 + mt * 16 + g;
#pragma unroll
        for (int nt = 0; nt < 4; nt++) {
            int col = wn * 32 + nt * 8 + tig * 2;
            *(float2*)&pa[(size_t)r0 * IN_DIM + col] = make_float2(d[mt][nt][0], d[mt][nt][1]);
            *(float2*)&pa[(size_t)(r0 + 8) * IN_DIM + col] = make_float2(d[mt][nt][2], d[mt][nt][3]);
        }
    }
}

// ---------------- 4b. combine: emb = elu(sum/den), split to bf16 hi+lo ----------------
__global__ __launch_bounds__(256) void combine_kernel() {
    int idx = blockIdx.x * 256 + threadIdx.x;        // float4 granularity
    int row = idx >> 5;
    float den = 0.f;
    float4 acc = make_float4(0.f, 0.f, 0.f, 0.f);
#pragma unroll
    for (int s = 0; s < NSPLIT; s++) {
        den += g_pden[(size_t)s * NROWS + row];
        float4 v = ((const float4*)g_pacc)[(size_t)s * NROWS * 32 + idx];
        acc.x += v.x; acc.y += v.y; acc.z += v.z; acc.w += v.w;
    }
    float inv = 1.0f / den;
    float o[4] = {acc.x * inv, acc.y * inv, acc.z * inv, acc.w * inv};
    __nv_bfloat16 hi[4], lo[4];
#pragma unroll
    for (int j = 0; j < 4; j++) {
        o[j] = o[j] > 0.f ? o[j] : expm1f(o[j]);
        hi[j] = __float2bfloat16(o[j]);
        lo[j] = __float2bfloat16(o[j] - __bfloat162float(hi[j]));
    }
    *(ull*)&g_embh[(size_t)idx * 4] = *(const ull*)hi;
    *(ull*)&g_embl[(size_t)idx * 4] = *(const ull*)lo;
}

// ---------------- 5. con_adj = emb @ emb.T via mma.sync bf16 split ----------------
#define LDB 136
#define TILE_ELEMS (128 * LDB)
#define SYRK_SMEM (4 * TILE_ELEMS * 2)

__device__ __forceinline__ void syrk_mma_phase(
    const __nv_bfloat16* Ah, const __nv_bfloat16* Al,
    const __nv_bfloat16* Bh, const __nv_bfloat16* Bl,
    int m0, int n0, int lane, float d[4][4][4]) {
#pragma unroll
    for (int pass = 0; pass < 3; pass++) {
        const __nv_bfloat16* Ap = (pass == 2) ? Al : Ah;
        const __nv_bfloat16* Bp = (pass == 1) ? Bl : Bh;
        uint32_t a_base = smem_u32(Ap);
        uint32_t b_base = smem_u32(Bp);
#pragma unroll
        for (int ks = 0; ks < 8; ks++) {
            int k0 = ks * 16;
            uint32_t afr[4][4], bfr[4][2];
#pragma unroll
            for (int mt = 0; mt < 4; mt++) {
                int row = m0 + mt * 16 + (lane & 15);
                int col = k0 + (lane >> 4) * 8;
                ldm_x4(afr[mt], a_base + (row * LDB + col) * 2);
            }
#pragma unroll
            for (int nt = 0; nt < 4; nt++) {
                int row = n0 + nt * 8 + (lane & 7);
                int col = k0 + ((lane >> 3) & 1) * 8;
                ldm_x2(bfr[nt], b_base + (row * LDB + col) * 2);
            }
#pragma unroll
            for (int mt = 0; mt < 4; mt++)
#pragma unroll
                for (int nt = 0; nt < 4; nt++)
                    mma16816(d[mt][nt], afr[mt], bfr[nt]);
        }
    }
}

__global__ __launch_bounds__(256) void syrk_mma_kernel(float* __restrict__ out) {
    const int bi = blockIdx.y, bj = blockIdx.x;
    if (bj < bi) return;
    extern __shared__ __nv_bfloat16 sm[];
    __nv_bfloat16* Ah = sm;
    __nv_bfloat16* Al = Ah + TILE_ELEMS;
    __nv_bfloat16* Bh = Al + TILE_ELEMS;
    __nv_bfloat16* Bl = Bh + TILE_ELEMS;

    const int tid = threadIdx.x;
    const int lane = tid & 31, wid = tid >> 5;
    const int i0 = bi * 128, j0 = bj * 128;
    const int m0 = (wid & 1) * 64, n0 = (wid >> 1) * 32;
    const int g = lane >> 2, tig = lane & 3;

    const uint4* EH = (const uint4*)g_embh;
    const uint4* EL = (const uint4*)g_embl;
#pragma unroll
    for (int e = 0; e < 8; e++) {
        int idx = tid + e * 256;
        int row = idx >> 4, ch = idx & 15;
        *(uint4*)&Ah[row * LDB + ch * 8] = EH[(size_t)(i0 + row) * 16 + ch];
        *(uint4*)&Al[row * LDB + ch * 8] = EL[(size_t)(i0 + row) * 16 + ch];
        *(uint4*)&Bh[row * LDB + ch * 8] = EH[(size_t)(j0 + row) * 16 + ch];
        *(uint4*)&Bl[row * LDB + ch * 8] = EL[(size_t)(j0 + row) * 16 + ch];
    }
    __syncthreads();

    float d[4][4][4];
#pragma unroll
    for (int mt = 0; mt < 4; mt++)
#pragma unroll
        for (int nt = 0; nt < 4; nt++)
#pragma unroll
            for (int q = 0; q < 4; q++) d[mt][nt][q] = 0.f;

    syrk_mma_phase(Ah, Al, Bh, Bl, m0, n0, lane, d);

#pragma unroll
    for (int mt = 0; mt < 4; mt++) {
        int r0 = i0 + m0 + mt * 16 + g;
#pragma unroll
        for (int nt = 0; nt < 4; nt++) {
            int c0 = j0 + n0 + nt * 8 + tig * 2;
            *(float2*)&out[(size_t)r0 * NROWS + c0] = make_float2(d[mt][nt][0], d[mt][nt][1]);
            *(float2*)&out[(size_t)(r0 + 8) * NROWS + c0] = make_float2(d[mt][nt][2], d[mt][nt][3]);
        }
    }

    if (bi != bj) {
#pragma unroll
        for (int mt = 0; mt < 4; mt++)
#pragma unroll
            for (int nt = 0; nt < 4; nt++)
#pragma unroll
                for (int q = 0; q < 4; q++) d[mt][nt][q] = 0.f;

        syrk_mma_phase(Bh, Bl, Ah, Al, m0, n0, lane, d);

#pragma unroll
        for (int mt = 0; mt < 4; mt++) {
            int r0 = j0 + m0 + mt * 16 + g;
#pragma unroll
            for (int nt = 0; nt < 4; nt++) {
                int c0 = i0 + n0 + nt * 8 + tig * 2;
                *(float2*)&out[(size_t)r0 * NROWS + c0] = make_float2(d[mt][nt][0], d[mt][nt][1]);
                *(float2*)&out[(size_t)(r0 + 8) * NROWS + c0] = make_float2(d[mt][nt][2], d[mt][nt][3]);
            }
        }
    }
}

// ---------------- 6. encoder: gates = x @ enc_W_ih.T, LSTM fused ----------------
__global__ __launch_bounds__(256) void enc_fused(const float* __restrict__ x,
                                                 const float* __restrict__ W,
                                                 const float* __restrict__ b_ih,
                                                 const float* __restrict__ b_hh) {
    __shared__ float As[16][128];
    __shared__ float Ws[16][257];
    __shared__ float gsm[16][256];
    const int i0 = blockIdx.x * 16;
    const int tid = threadIdx.x;
    const int n = tid;

    for (int idx = tid; idx < 16 * 128; idx += 256)
        As[idx >> 7][idx & 127] = x[(size_t)(i0 + (idx >> 7)) * 128 + (idx & 127)];

    float acc[16];
#pragma unroll
    for (int r = 0; r < 16; r++) acc[r] = 0.f;

    for (int kt = 0; kt < 128; kt += 16) {
        __syncthreads();
        for (int f = tid; f < 16 * 256; f += 256) {
            int n2 = f >> 4, kk = f & 15;
            Ws[kk][n2] = W[(size_t)n2 * 128 + kt + kk];
        }
        __syncthreads();
#pragma unroll
        for (int kk = 0; kk < 16; kk++) {
            float b = Ws[kk][n];
#pragma unroll
            for (int r = 0; r < 16; r++) acc[r] += As[r][kt + kk] * b;
        }
    }
    __syncthreads();
#pragma unroll
    for (int r = 0; r < 16; r++) gsm[r][n] = acc[r];
    __syncthreads();

#pragma unroll
    for (int e = 0; e < 4; e++) {
        int idx = tid + e * 256;
        int row = idx >> 6, hh = idx & 63;
        float gi = gsm[row][hh] + b_ih[hh] + b_hh[hh];
        float gg = gsm[row][128 + hh] + b_ih[128 + hh] + b_hh[128 + hh];
        float go = gsm[row][192 + hh] + b_ih[192 + hh] + b_hh[192 + hh];
        float c = sigmoidf_(gi) * tanhf(gg);
        g_henc[(size_t)(i0 + row) * 64 + hh] = sigmoidf_(go) * tanhf(c);
    }
}

// ---------------- 7. decoder: gates = h_enc @ dec_W_ih.T, LSTM fused ----------------
__global__ __launch_bounds__(512) void dec_fused(const float* __restrict__ W,
                                                 const float* __restrict__ b_ih,
                                                 const float* __restrict__ b_hh,
                                                 float* __restrict__ out) {
    __shared__ union {
        struct { float As[16][64]; float Ws[16][513]; } in;
        float gsm[16][512];
    } sm;
    const int i0 = blockIdx.x * 16;
    const int tid = threadIdx.x;
    const int n = tid;

    for (int idx = tid; idx < 16 * 64; idx += 512)
        sm.in.As[idx >> 6][idx & 63] = g_henc[(size_t)(i0 + (idx >> 6)) * 64 + (idx & 63)];

    float acc[16];
#pragma unroll
    for (int r = 0; r < 16; r++) acc[r] = 0.f;

    for (int kt = 0; kt < 64; kt += 16) {
        __syncthreads();
        for (int f = tid; f < 16 * 512; f += 512) {
            int n2 = f >> 4, kk = f & 15;
            sm.in.Ws[kk][n2] = W[(size_t)n2 * 64 + kt + kk];
        }
        __syncthreads();
#pragma unroll
        for (int kk = 0; kk < 16; kk++) {
            float b = sm.in.Ws[kk][n];
#pragma unroll
            for (int r = 0; r < 16; r++) acc[r] += sm.in.As[r][kt + kk] * b;
        }
    }
    __syncthreads();
#pragma unroll
    for (int r = 0; r < 16; r++) sm.gsm[r][n] = acc[r];
    __syncthreads();

#pragma unroll
    for (int e = 0; e < 4; e++) {
        int idx = tid + e * 512;
        int row = idx >> 7, hh = idx & 127;
        float gi = sm.gsm[row][hh] + b_ih[hh] + b_hh[hh];
        float gg = sm.gsm[row][256 + hh] + b_ih[256 + hh] + b_hh[256 + hh];
        float go = sm.gsm[row][384 + hh] + b_ih[384 + hh] + b_hh[384 + hh];
        float c = sigmoidf_(gi) * tanhf(gg);
        out[(size_t)(i0 + row) * 128 + hh] = sigmoidf_(go) * tanhf(c);
    }
}

// ---------------- launch ----------------
extern "C" void kernel_launch(void* const* d_in, const int* in_sizes, int n_in,
                              void* d_out, int out_size) {
    const float* x = (const float*)d_in[0];
    const float* adj = (const float*)d_in[1];
    const float* fea_W = (const float*)d_in[2];
    const float* fea_b = (const float*)d_in[3];
    const float* gat_W = (const float*)d_in[4];
    const float* gat_a = (const float*)d_in[5];
    const float* enc_W_ih = (const float*)d_in[6];
    const float* enc_b_ih = (const float*)d_in[8];
    const float* enc_b_hh = (const float*)d_in[9];
    const float* dec_W_ih = (const float*)d_in[10];
    const float* dec_b_ih = (const float*)d_in[12];
    const float* dec_b_hh = (const float*)d_in[13];

    float* out = (float*)d_out;
    float* con_adj = out;
    float* att_adj = out + (size_t)NROWS * NROWS;

    cudaFuncSetAttribute(syrk_mma_kernel, cudaFuncAttributeMaxDynamicSharedMemorySize, SYRK_SMEM);

    struct_kernel<<<NROWS / 16, 256>>>(x, fea_W, fea_b);                    // 1
    wh_s1s2_kernel<<<NROWS / 16, 256>>>(gat_W, gat_a);                      // 2
    vec_kernel<<<NROWS / 256, 256>>>();                                     // 3
    attn_mma_kernel<<<dim3(NROWS / 64, NSPLIT), 256>>>(adj);                // 4  <- ncu slot
    combine_kernel<<<NROWS * 32 / 256, 256>>>();                            // 5
    syrk_mma_kernel<<<dim3(64, 64), 256, SYRK_SMEM>>>(con_adj);             // 6
    enc_fused<<<NROWS / 16, 256>>>(x, enc_W_ih, enc_b_ih, enc_b_hh);        // 7
    dec_fused<<<NROWS / 16, 512>>>(dec_W_ih, dec_b_ih, dec_b_hh, att_adj);  // 8
}

// round 10
// speedup vs baseline: 2.7875x; 1.0095x over previous
#include <cuda_runtime.h>
#include <cuda_bf16.h>
#include <cstdint>

#define NROWS 8192
#define IN_DIM 128
#define HID 64
#define NSPLIT 16
#define JSEG (NROWS / NSPLIT)

typedef unsigned long long ull;

// ---------------- scratch (static device globals; no allocation) ----------------
__device__ __align__(16) float g_struct[NROWS * HID];
__device__ __align__(16) __nv_bfloat16 g_Whh[NROWS * IN_DIM];
__device__ __align__(16) __nv_bfloat16 g_Whl[NROWS * IN_DIM];
__device__ __align__(16) float g_s1[NROWS];
__device__ __align__(16) float g_s2[NROWS];
__device__ __align__(16) float g_A[NROWS];
__device__ __align__(16) float g_B[NROWS];
__device__ __align__(16) float g_C[NROWS];
__device__ __align__(16) float g_D[NROWS];
__device__ unsigned g_s2max_bits = 0u;
__device__ __align__(16) float g_henc[NROWS * HID];
__device__ __align__(16) __nv_bfloat16 g_embh[NROWS * IN_DIM];
__device__ __align__(16) __nv_bfloat16 g_embl[NROWS * IN_DIM];
__device__ __align__(16) float g_pacc[NSPLIT * NROWS * IN_DIM];
__device__ __align__(16) float g_pden[NSPLIT * NROWS];

// ---------------- helpers ----------------
__device__ __forceinline__ float sigmoidf_(float x) { return 1.0f / (1.0f + __expf(-x)); }

__device__ __forceinline__ unsigned float_key(float f) {
    unsigned b = __float_as_uint(f);
    return (b & 0x80000000u) ? ~b : (b | 0x80000000u);
}
__device__ __forceinline__ float key_float(unsigned k) {
    unsigned b = (k & 0x80000000u) ? (k & 0x7fffffffu) : ~k;
    return __uint_as_float(b);
}
__device__ __forceinline__ uint32_t smem_u32(const void* p) {
    uint32_t a;
    asm("{ .reg .u64 t; cvta.to.shared.u64 t, %1; cvt.u32.u64 %0, t; }" : "=r"(a) : "l"(p));
    return a;
}

#define CP_ASYNC16(dst, src) asm volatile("cp.async.cg.shared.global [%0], [%1], 16;" :: "r"(dst), "l"(src))
#define CP_COMMIT() asm volatile("cp.async.commit_group;" ::: "memory")
#define CP_WAIT0() asm volatile("cp.async.wait_group 0;" ::: "memory")

// ---------------- mma.sync helpers (bf16, m16n8k16) ----------------
__device__ __forceinline__ void ldm_x4(uint32_t* a, uint32_t addr) {
    asm volatile("ldmatrix.sync.aligned.m8n8.x4.shared.b16 {%0,%1,%2,%3}, [%4];"
                 : "=r"(a[0]), "=r"(a[1]), "=r"(a[2]), "=r"(a[3]) : "r"(addr));
}
__device__ __forceinline__ void ldm_x4t(uint32_t* a, uint32_t addr) {
    asm volatile("ldmatrix.sync.aligned.m8n8.x4.trans.shared.b16 {%0,%1,%2,%3}, [%4];"
                 : "=r"(a[0]), "=r"(a[1]), "=r"(a[2]), "=r"(a[3]) : "r"(addr));
}
__device__ __forceinline__ void ldm_x2(uint32_t* b, uint32_t addr) {
    asm volatile("ldmatrix.sync.aligned.m8n8.x2.shared.b16 {%0,%1}, [%2];"
                 : "=r"(b[0]), "=r"(b[1]) : "r"(addr));
}
__device__ __forceinline__ void mma16816(float* d, const uint32_t* a, const uint32_t* b) {
    asm volatile("mma.sync.aligned.m16n8k16.row.col.f32.bf16.bf16.f32 "
                 "{%0,%1,%2,%3}, {%4,%5,%6,%7}, {%8,%9}, {%0,%1,%2,%3};"
                 : "+f"(d[0]), "+f"(d[1]), "+f"(d[2]), "+f"(d[3])
                 : "r"(a[0]), "r"(a[1]), "r"(a[2]), "r"(a[3]), "r"(b[0]), "r"(b[1]));
}

// ---------------- 1. structure = relu(x @ fea_W + fea_b) ----------------
__global__ __launch_bounds__(256) void struct_kernel(const float* __restrict__ A,
                                                     const float* __restrict__ W,
                                                     const float* __restrict__ bias) {
    __shared__ float As[16][128];
    const int i0 = blockIdx.x * 16;
    const int tid = threadIdx.x;
    const int n = tid & 63, rg = tid >> 6;

    for (int idx = tid; idx < 16 * 128; idx += 256)
        As[idx >> 7][idx & 127] = A[(size_t)(i0 + (idx >> 7)) * 128 + (idx & 127)];
    __syncthreads();

    float acc[4] = {0.f, 0.f, 0.f, 0.f};
#pragma unroll 4
    for (int k = 0; k < 128; k++) {
        float b = W[(size_t)k * 64 + n];
#pragma unroll
        for (int r = 0; r < 4; r++) acc[r] += As[rg * 4 + r][k] * b;
    }
    float bv = bias[n];
#pragma unroll
    for (int r = 0; r < 4; r++)
        g_struct[(size_t)(i0 + rg * 4 + r) * 64 + n] = fmaxf(acc[r] + bv, 0.f);
}

// ---------------- 2. Wh = structure @ gat_W (bf16 hi/lo), fused s1/s2/max(s2) ----------------
__global__ __launch_bounds__(256) void wh_s1s2_kernel(const float* __restrict__ W,
                                                      const float* __restrict__ gat_a) {
    __shared__ float As[16][64];
    __shared__ float r1[8][8], r2[8][8];
    const int i0 = blockIdx.x * 16;
    const int tid = threadIdx.x;
    const int n = tid & 127, rg = tid >> 7;

    for (int idx = tid; idx < 16 * 64; idx += 256)
        As[idx >> 6][idx & 63] = g_struct[(size_t)(i0 + (idx >> 6)) * 64 + (idx & 63)];
    __syncthreads();

    float acc[8];
#pragma unroll
    for (int r = 0; r < 8; r++) acc[r] = 0.f;
#pragma unroll 4
    for (int k = 0; k < 64; k++) {
        float b = W[(size_t)k * 128 + n];
#pragma unroll
        for (int r = 0; r < 8; r++) acc[r] += As[rg * 8 + r][k] * b;
    }
#pragma unroll
    for (int r = 0; r < 8; r++) {
        float v = acc[r];
        __nv_bfloat16 hi = __float2bfloat16(v);
        __nv_bfloat16 lo = __float2bfloat16(v - __bfloat162float(hi));
        g_Whh[(size_t)(i0 + rg * 8 + r) * 128 + n] = hi;
        g_Whl[(size_t)(i0 + rg * 8 + r) * 128 + n] = lo;
    }

    float a1v = gat_a[n], a2v = gat_a[128 + n];
    int warp = tid >> 5, lane = tid & 31;
#pragma unroll
    for (int r = 0; r < 8; r++) {
        float v1 = acc[r] * a1v, v2 = acc[r] * a2v;
#pragma unroll
        for (int off = 16; off; off >>= 1) {
            v1 += __shfl_xor_sync(0xffffffffu, v1, off);
            v2 += __shfl_xor_sync(0xffffffffu, v2, off);
        }
        if (lane == 0) { r1[warp][r] = v1; r2[warp][r] = v2; }
    }
    __syncthreads();
    if (tid < 16) {
        int rgg = tid >> 3, rr = tid & 7;
        float s1 = r1[rgg * 4 + 0][rr] + r1[rgg * 4 + 1][rr] + r1[rgg * 4 + 2][rr] + r1[rgg * 4 + 3][rr];
        float s2 = r2[rgg * 4 + 0][rr] + r2[rgg * 4 + 1][rr] + r2[rgg * 4 + 2][rr] + r2[rgg * 4 + 3][rr];
        g_s1[i0 + tid] = s1;
        g_s2[i0 + tid] = s2;
        float m = s2;
#pragma unroll
        for (int off = 8; off; off >>= 1) m = fmaxf(m, __shfl_xor_sync(0x0000ffffu, m, off));
        if (tid == 0) atomicMax(&g_s2max_bits, float_key(m));
    }
}

// ---------------- 3. precompute A,B,C,D ----------------
__global__ void vec_kernel() {
    int i = blockIdx.x * 256 + threadIdx.x;
    float s2max = key_float(g_s2max_bits);
    float t = g_s1[i] + s2max;
    float m = t > 0.f ? t : 0.2f * t;
    g_A[i] = expf(t - m);
    g_C[i] = expf(0.2f * t - m);
    float u = g_s2[i] - s2max;
    g_B[i] = expf(u);
    g_D[i] = expf(0.2f * u);
}

// ---------------- 4. attention partial: cp.async pipelined mma split-bf16 ----------------
// Block 64(i) x 128(c); chunk 32 j. Double-buffered adj/Wh/s2BD via cp.async.
#define PLD 40
#define WLD 136
#define WHH_OFF(b) ((b) * 8704)
#define WHL_OFF(b) (17408 + (b) * 8704)
#define ADJ_OFF(b) (34816 + (b) * 9216)
#define PH_OFF 53248
#define PL_OFF 58368
#define S2BD_OFF(b) (63488 + (b) * 384)
#define SAC_OFF 64256
#define ATTN_SMEM 65024

__global__ __launch_bounds__(256) void attn_mma_kernel(const float* __restrict__ adj) {
    extern __shared__ __align__(16) char smem[];
    const uint32_t sb = smem_u32(smem);
    float* sac = (float*)(smem + SAC_OFF);   // s1[64], A[64], C[64]

    const int i0 = blockIdx.x * 64;
    const int jb = blockIdx.y * JSEG;
    const int tid = threadIdx.x;
    const int lane = tid & 31, wid = tid >> 5;
    const int wm = wid & 1, wn = wid >> 1;
    if (tid < 64) {
        sac[tid] = g_s1[i0 + tid];
        sac[64 + tid] = g_A[i0 + tid];
        sac[128 + tid] = g_C[i0 + tid];
    }

    const int c4 = (tid & 7) * 4;
    const int rp = tid >> 3;

    float d[2][4][4];
#pragma unroll
    for (int mt = 0; mt < 2; mt++)
#pragma unroll
        for (int nt = 0; nt < 4; nt++)
#pragma unroll
            for (int q = 0; q < 4; q++) d[mt][nt][q] = 0.f;
    float dsum[2] = {0.f, 0.f};

    const int whrow = tid >> 4, whch = tid & 15;     // +e*16 rows
    const int adrow = tid >> 3, adch = tid & 7;      // +e*32 rows

    // cp.async issue for chunk t into buffer b
    auto issue_cp = [&](int t) {
        int b = t & 1;
        int jc = jb + t * 32;
#pragma unroll
        for (int e = 0; e < 2; e++) {
            int row = whrow + e * 16;
            CP_ASYNC16(sb + WHH_OFF(b) + row * 272 + whch * 16,
                       (const char*)g_Whh + ((size_t)(jc + row) * 128 + whch * 8) * 2);
            CP_ASYNC16(sb + WHL_OFF(b) + row * 272 + whch * 16,
                       (const char*)g_Whl + ((size_t)(jc + row) * 128 + whch * 8) * 2);
            int arow = adrow + e * 32;
            CP_ASYNC16(sb + ADJ_OFF(b) + arow * 144 + adch * 16,
                       (const char*)adj + ((size_t)(i0 + arow) * NROWS + jc + adch * 4) * 4);
        }
        if (tid < 24) {
            int arr = tid >> 3, sub = tid & 7;
            const float* src = arr == 0 ? g_s2 : (arr == 1 ? g_B : g_D);
            CP_ASYNC16(sb + S2BD_OFF(b) + arr * 128 + sub * 16,
                       (const char*)(src + jc + sub * 4));
        }
    };

    issue_cp(0);
    CP_COMMIT();

    const int T = JSEG / 32;
    for (int t = 0; t < T; t++) {
        const int b = t & 1;
        CP_WAIT0();
        __syncthreads();           // chunk t resident; also orders mma(t-1) before transform(t)
        if (t + 1 < T) { issue_cp(t + 1); CP_COMMIT(); }

        // transform: adj smem -> p hi/lo bf16 tiles
        {
            const float* s2bd = (const float*)(smem + S2BD_OFF(b));
            float4 s2v = ((const float4*)s2bd)[tid & 7];
            float4 Bv = ((const float4*)(s2bd + 32))[tid & 7];
            float4 Dv = ((const float4*)(s2bd + 64))[tid & 7];
            const float* adjs = (const float*)(smem + ADJ_OFF(b));
#pragma unroll
            for (int rr = 0; rr < 2; rr++) {
                int r = rp * 2 + rr;
                float4 av = *(const float4*)&adjs[r * 36 + c4];
                float s1 = sac[r], Av = sac[64 + r], Cv = sac[128 + r];
                float pv[4];
                { float tt = s1 + s2v.x; pv[0] = (av.x > 0.f) ? (tt > 0.f ? Av * Bv.x : Cv * Dv.x) : 0.f; }
                { float tt = s1 + s2v.y; pv[1] = (av.y > 0.f) ? (tt > 0.f ? Av * Bv.y : Cv * Dv.y) : 0.f; }
                { float tt = s1 + s2v.z; pv[2] = (av.z > 0.f) ? (tt > 0.f ? Av * Bv.z : Cv * Dv.z) : 0.f; }
                { float tt = s1 + s2v.w; pv[3] = (av.w > 0.f) ? (tt > 0.f ? Av * Bv.w : Cv * Dv.w) : 0.f; }
                ushort4 h4, l4;
                unsigned short* hp = (unsigned short*)&h4;
                unsigned short* lp = (unsigned short*)&l4;
#pragma unroll
                for (int q = 0; q < 4; q++) {
                    __nv_bfloat16 hi = __float2bfloat16(pv[q]);
                    __nv_bfloat16 lo = __float2bfloat16(pv[q] - __bfloat162float(hi));
                    hp[q] = *(unsigned short*)&hi;
                    lp[q] = *(unsigned short*)&lo;
                }
                *(ushort4*)(smem + PH_OFF + (r * PLD + c4) * 2) = h4;
                *(ushort4*)(smem + PL_OFF + (r * PLD + c4) * 2) = l4;
                dsum[rr] += (pv[0] + pv[1]) + (pv[2] + pv[3]);
            }
        }
        __syncthreads();

        // mma: d += ph*Whh + pl*Whh + ph*Whl
        const uint32_t ph_b = sb + PH_OFF, pl_b = sb + PL_OFF;
        const uint32_t whh_b = sb + WHH_OFF(b), whl_b = sb + WHL_OFF(b);
#pragma unroll
        for (int ks = 0; ks < 2; ks++) {
            int k0 = ks * 16;
            uint32_t aph[2][4], apl[2][4], bhh[2][4], bhl[2][4];
#pragma unroll
            for (int mt = 0; mt < 2; mt++) {
                uint32_t off = ((wm * 32 + mt * 16 + (lane & 15)) * PLD + k0 + (lane >> 4) * 8) * 2;
                ldm_x4(aph[mt], ph_b + off);
                ldm_x4(apl[mt], pl_b + off);
            }
#pragma unroll
            for (int np = 0; np < 2; np++) {
                uint32_t off = ((k0 + (lane & 15)) * WLD + wn * 32 + np * 16 + (lane >> 4) * 8) * 2;
                ldm_x4t(bhh[np], whh_b + off);
                ldm_x4t(bhl[np], whl_b + off);
            }
#pragma unroll
            for (int mt = 0; mt < 2; mt++)
#pragma unroll
                for (int np = 0; np < 2; np++)
#pragma unroll
                    for (int h = 0; h < 2; h++) {
                        int nt = np * 2 + h;
                        mma16816(d[mt][nt], aph[mt], &bhh[np][h * 2]);
                        mma16816(d[mt][nt], apl[mt], &bhh[np][h * 2]);
                        mma16816(d[mt][nt], aph[mt], &bhl[np][h * 2]);
                    }
        }
    }

#pragma unroll
    for (int off = 4; off; off >>= 1) {
        dsum[0] += __shfl_down_sync(0xffffffffu, dsum[0], off, 8);
        dsum[1] += __shfl_down_sync(0xffffffffu, dsum[1], off, 8);
    }
    if ((tid & 7) == 0) {
        g_pden[(size_t)blockIdx.y * NROWS + i0 + rp * 2] = dsum[0];
        g_pden[(size_t)blockIdx.y * NROWS + i0 + rp * 2 + 1] = dsum[1];
    }

    float* pa = g_pacc + (size_t)blockIdx.y * NROWS * IN_DIM;
    const int g = lane >> 2, tig = lane & 3;
#pragma unroll
    for (int mt = 0; mt < 2; mt++) {
        int r0 = i0 + wm * 32 + mt * 16 + g;
#pragma unroll
        for (int nt = 0; nt < 4; nt++) {
            int col = wn * 32 + nt * 8 + tig * 2;
            *(float2*)&pa[(size_t)r0 * IN_DIM + col] = make_float2(d[mt][nt][0], d[mt][nt][1]);
            *(float2*)&pa[(size_t)(r0 + 8) * IN_DIM + col] = make_float2(d[mt][nt][2], d[mt][nt][3]);
        }
    }
}

// ---------------- 4b. combine: emb = elu(sum/den), split to bf16 hi+lo ----------------
__global__ __launch_bounds__(256) void combine_kernel() {
    int idx = blockIdx.x * 256 + threadIdx.x;
    int row = idx >> 5;
    float den = 0.f;
    float4 acc = make_float4(0.f, 0.f, 0.f, 0.f);
#pragma unroll
    for (int s = 0; s < NSPLIT; s++) {
        den += g_pden[(size_t)s * NROWS + row];
        float4 v = ((const float4*)g_pacc)[(size_t)s * NROWS * 32 + idx];
        acc.x += v.x; acc.y += v.y; acc.z += v.z; acc.w += v.w;
    }
    float inv = 1.0f / den;
    float o[4] = {acc.x * inv, acc.y * inv, acc.z * inv, acc.w * inv};
    __nv_bfloat16 hi[4], lo[4];
#pragma unroll
    for (int j = 0; j < 4; j++) {
        o[j] = o[j] > 0.f ? o[j] : expm1f(o[j]);
        hi[j] = __float2bfloat16(o[j]);
        lo[j] = __float2bfloat16(o[j] - __bfloat162float(hi[j]));
    }
    *(ull*)&g_embh[(size_t)idx * 4] = *(const ull*)hi;
    *(ull*)&g_embl[(size_t)idx * 4] = *(const ull*)lo;
}

// ---------------- 5. con_adj = emb @ emb.T, 2-tile staged smem, mma split-bf16 ----------------
#define LDB 136
#define TILE_ELEMS (128 * LDB)
#define SYRK_SMEM (2 * TILE_ELEMS * 2)

__device__ __forceinline__ void syrk_load_tile(char* dst, const __nv_bfloat16* src, int row0, int tid) {
#pragma unroll
    for (int e = 0; e < 8; e++) {
        int idx = tid + e * 256;
        int row = idx >> 4, ch = idx & 15;
        CP_ASYNC16(smem_u32(dst) + row * (LDB * 2) + ch * 16,
                   (const char*)src + ((size_t)(row0 + row) * 128 + ch * 8) * 2);
    }
    CP_COMMIT();
}

// d += frA(X[m0...]) * frB(Y[n0...])^T over K=128
__device__ __forceinline__ void syrk_pass(uint32_t x_b, uint32_t y_b, int m0, int n0,
                                          int lane, float d[4][4][4]) {
#pragma unroll
    for (int ks = 0; ks < 8; ks++) {
        int k0 = ks * 16;
        uint32_t afr[4][4], bfr[4][2];
#pragma unroll
        for (int mt = 0; mt < 4; mt++) {
            int row = m0 + mt * 16 + (lane & 15);
            int col = k0 + (lane >> 4) * 8;
            ldm_x4(afr[mt], x_b + (row * LDB + col) * 2);
        }
#pragma unroll
        for (int nt = 0; nt < 4; nt++) {
            int row = n0 + nt * 8 + (lane & 7);
            int col = k0 + ((lane >> 3) & 1) * 8;
            ldm_x2(bfr[nt], y_b + (row * LDB + col) * 2);
        }
#pragma unroll
        for (int mt = 0; mt < 4; mt++)
#pragma unroll
            for (int nt = 0; nt < 4; nt++)
                mma16816(d[mt][nt], afr[mt], bfr[nt]);
    }
}

__device__ __forceinline__ void syrk_store(float* out, int r_base, int c_base,
                                           int m0, int n0, int lane, float d[4][4][4]) {
    const int g = lane >> 2, tig = lane & 3;
#pragma unroll
    for (int mt = 0; mt < 4; mt++) {
        int r0 = r_base + m0 + mt * 16 + g;
#pragma unroll
        for (int nt = 0; nt < 4; nt++) {
            int c0 = c_base + n0 + nt * 8 + tig * 2;
            *(float2*)&out[(size_t)r0 * NROWS + c0] = make_float2(d[mt][nt][0], d[mt][nt][1]);
            *(float2*)&out[(size_t)(r0 + 8) * NROWS + c0] = make_float2(d[mt][nt][2], d[mt][nt][3]);
        }
    }
}

__global__ __launch_bounds__(256) void syrk_mma_kernel(float* __restrict__ out) {
    const int bi = blockIdx.y, bj = blockIdx.x;
    if (bj < bi) return;
    extern __shared__ __align__(16) char smem[];
    char* T0 = smem;
    char* T1 = smem + TILE_ELEMS * 2;
    const uint32_t t0_b = smem_u32(T0), t1_b = smem_u32(T1);

    const int tid = threadIdx.x;
    const int lane = tid & 31, wid = tid >> 5;
    const int i0 = bi * 128, j0 = bj * 128;
    const int m0 = (wid & 1) * 64, n0 = (wid >> 1) * 32;

    float d[4][4][4];
#pragma unroll
    for (int mt = 0; mt < 4; mt++)
#pragma unroll
        for (int nt = 0; nt < 4; nt++)
#pragma unroll
            for (int q = 0; q < 4; q++) d[mt][nt][q] = 0.f;

    // Phase D = A * B^T : stages {Ah,Bh} -> {Ah,Bl} -> {Al,Bh}
    syrk_load_tile(T0, g_embh, i0, tid);
    syrk_load_tile(T1, g_embh, j0, tid);
    CP_WAIT0(); __syncthreads();
    syrk_pass(t0_b, t1_b, m0, n0, lane, d);

    __syncthreads();
    syrk_load_tile(T1, g_embl, j0, tid);
    CP_WAIT0(); __syncthreads();
    syrk_pass(t0_b, t1_b, m0, n0, lane, d);

    __syncthreads();
    syrk_load_tile(T0, g_embl, i0, tid);
    syrk_load_tile(T1, g_embh, j0, tid);
    CP_WAIT0(); __syncthreads();
    syrk_pass(t0_b, t1_b, m0, n0, lane, d);

    syrk_store(out, i0, j0, m0, n0, lane, d);

    if (bi != bj) {
        // Phase D' = B * A^T : resident {Al, Bh}; stages Bh*Al^T -> Bh*Ah^T -> Bl*Ah^T
#pragma unroll
        for (int mt = 0; mt < 4; mt++)
#pragma unroll
            for (int nt = 0; nt < 4; nt++)
#pragma unroll
                for (int q = 0; q < 4; q++) d[mt][nt][q] = 0.f;

        syrk_pass(t1_b, t0_b, m0, n0, lane, d);

        __syncthreads();
        syrk_load_tile(T0, g_embh, i0, tid);
        CP_WAIT0(); __syncthreads();
        syrk_pass(t1_b, t0_b, m0, n0, lane, d);

        __syncthreads();
        syrk_load_tile(T1, g_embl, j0, tid);
        CP_WAIT0(); __syncthreads();
        syrk_pass(t1_b, t0_b, m0, n0, lane, d);

        syrk_store(out, j0, i0, m0, n0, lane, d);
    }
}

// ---------------- 6. encoder: gates = x @ enc_W_ih.T, LSTM fused ----------------
__global__ __launch_bounds__(256) void enc_fused(const float* __restrict__ x,
                                                 const float* __restrict__ W,
                                                 const float* __restrict__ b_ih,
                                                 const float* __restrict__ b_hh) {
    __shared__ float As[16][128];
    __shared__ float Ws[16][257];
    __shared__ float gsm[16][256];
    const int i0 = blockIdx.x * 16;
    const int tid = threadIdx.x;
    const int n = tid;

    for (int idx = tid; idx < 16 * 128; idx += 256)
        As[idx >> 7][idx & 127] = x[(size_t)(i0 + (idx >> 7)) * 128 + (idx & 127)];

    float acc[16];
#pragma unroll
    for (int r = 0; r < 16; r++) acc[r] = 0.f;

    for (int kt = 0; kt < 128; kt += 16) {
        __syncthreads();
        for (int f = tid; f < 16 * 256; f += 256) {
            int n2 = f >> 4, kk = f & 15;
            Ws[kk][n2] = W[(size_t)n2 * 128 + kt + kk];
        }
        __syncthreads();
#pragma unroll
        for (int kk = 0; kk < 16; kk++) {
            float b = Ws[kk][n];
#pragma unroll
            for (int r = 0; r < 16; r++) acc[r] += As[r][kt + kk] * b;
        }
    }
    __syncthreads();
#pragma unroll
    for (int r = 0; r < 16; r++) gsm[r][n] = acc[r];
    __syncthreads();

#pragma unroll
    for (int e = 0; e < 4; e++) {
        int idx = tid + e * 256;
        int row = idx >> 6, hh = idx & 63;
        float gi = gsm[row][hh] + b_ih[hh] + b_hh[hh];
        float gg = gsm[row][128 + hh] + b_ih[128 + hh] + b_hh[128 + hh];
        float go = gsm[row][192 + hh] + b_ih[192 + hh] + b_hh[192 + hh];
        float c = sigmoidf_(gi) * tanhf(gg);
        g_henc[(size_t)(i0 + row) * 64 + hh] = sigmoidf_(go) * tanhf(c);
    }
}

// ---------------- 7. decoder: gates = h_enc @ dec_W_ih.T, LSTM fused ----------------
__global__ __launch_bounds__(512) void dec_fused(const float* __restrict__ W,
                                                 const float* __restrict__ b_ih,
                                                 const float* __restrict__ b_hh,
                                                 float* __restrict__ out) {
    __shared__ union {
        struct { float As[16][64]; float Ws[16][513]; } in;
        float gsm[16][512];
    } sm;
    const int i0 = blockIdx.x * 16;
    const int tid = threadIdx.x;
    const int n = tid;

    for (int idx = tid; idx < 16 * 64; idx += 512)
        sm.in.As[idx >> 6][idx & 63] = g_henc[(size_t)(i0 + (idx >> 6)) * 64 + (idx & 63)];

    float acc[16];
#pragma unroll
    for (int r = 0; r < 16; r++) acc[r] = 0.f;

    for (int kt = 0; kt < 64; kt += 16) {
        __syncthreads();
        for (int f = tid; f < 16 * 512; f += 512) {
            int n2 = f >> 4, kk = f & 15;
            sm.in.Ws[kk][n2] = W[(size_t)n2 * 64 + kt + kk];
        }
        __syncthreads();
#pragma unroll
        for (int kk = 0; kk < 16; kk++) {
            float b = sm.in.Ws[kk][n];
#pragma unroll
            for (int r = 0; r < 16; r++) acc[r] += sm.in.As[r][kt + kk] * b;
        }
    }
    __syncthreads();
#pragma unroll
    for (int r = 0; r < 16; r++) sm.gsm[r][n] = acc[r];
    __syncthreads();

#pragma unroll
    for (int e = 0; e < 4; e++) {
        int idx = tid + e * 512;
        int row = idx >> 7, hh = idx & 127;
        float gi = sm.gsm[row][hh] + b_ih[hh] + b_hh[hh];
        float gg = sm.gsm[row][256 + hh] + b_ih[256 + hh] + b_hh[256 + hh];
        float go = sm.gsm[row][384 + hh] + b_ih[384 + hh] + b_hh[384 + hh];
        float c = sigmoidf_(gi) * tanhf(gg);
        out[(size_t)(i0 + row) * 128 + hh] = sigmoidf_(go) * tanhf(c);
    }
}

// ---------------- launch ----------------
extern "C" void kernel_launch(void* const* d_in, const int* in_sizes, int n_in,
                              void* d_out, int out_size) {
    const float* x = (const float*)d_in[0];
    const float* adj = (const float*)d_in[1];
    const float* fea_W = (const float*)d_in[2];
    const float* fea_b = (const float*)d_in[3];
    const float* gat_W = (const float*)d_in[4];
    const float* gat_a = (const float*)d_in[5];
    const float* enc_W_ih = (const float*)d_in[6];
    const float* enc_b_ih = (const float*)d_in[8];
    const float* enc_b_hh = (const float*)d_in[9];
    const float* dec_W_ih = (const float*)d_in[10];
    const float* dec_b_ih = (const float*)d_in[12];
    const float* dec_b_hh = (const float*)d_in[13];

    float* out = (float*)d_out;
    float* con_adj = out;
    float* att_adj = out + (size_t)NROWS * NROWS;

    cudaFuncSetAttribute(attn_mma_kernel, cudaFuncAttributeMaxDynamicSharedMemorySize, ATTN_SMEM);
    cudaFuncSetAttribute(syrk_mma_kernel, cudaFuncAttributeMaxDynamicSharedMemorySize, SYRK_SMEM);

    struct_kernel<<<NROWS / 16, 256>>>(x, fea_W, fea_b);                    // 1
    wh_s1s2_kernel<<<NROWS / 16, 256>>>(gat_W, gat_a);                      // 2
    vec_kernel<<<NROWS / 256, 256>>>();                                     // 3
    attn_mma_kernel<<<dim3(NROWS / 64, NSPLIT), 256, ATTN_SMEM>>>(adj);     // 4  <- ncu slot
    combine_kernel<<<NROWS * 32 / 256, 256>>>();                            // 5
    syrk_mma_kernel<<<dim3(64, 64), 256, SYRK_SMEM>>>(con_adj);             // 6
    enc_fused<<<NROWS / 16, 256>>>(x, enc_W_ih, enc_b_ih, enc_b_hh);        // 7
    dec_fused<<<NROWS / 16, 512>>>(dec_W_ih, dec_b_ih, dec_b_hh, att_adj);  // 8
}